// round 2
// baseline (speedup 1.0000x reference)
#include <cuda_runtime.h>
#include <math.h>

// ----------------------------------------------------------------------------
// SlotRNN: 2-layer GRU (B=16, T=1024, H=1024) + linear(128) + log_softmax(axis=1)
//
// Pipeline:
//   1. gemm_tn (gather): gx = emb[tok] @ W_ih_l0^T + b_ih_l0          [16384, 3072]
//   2. scan_kernel:      layer-0 recurrence -> hseq (h1)              [16384, 1024]
//   3. gemm_tn:          gx = hseq @ W_ih_l1^T + b_ih_l1
//   4. scan_kernel:      layer-1 recurrence -> hseq (h2, overwrites)
//   5. gemm_tn:          d_out = hseq @ W_lin^T + b_lin (logits)      [16384, 128]
//   6. lse_kernel:       lse[b,c] = logsumexp over t of logits[b,t,c]
//   7. sub_kernel:       d_out[b,t,c] -= lse[b,c]
// ----------------------------------------------------------------------------

#define BATCH 16
#define TSEQ  1024
#define HD    1024
#define MTOT  (BATCH * TSEQ)   // 16384
#define G3H   (3 * HD)         // 3072
#define NCLS  128

// Scratch (device globals: no runtime allocation allowed)
__device__ float g_gx[(size_t)MTOT * G3H];     // 192 MB
__device__ float g_hseq[(size_t)MTOT * HD];    // 64 MB
__device__ float g_lse[BATCH * NCLS];
__device__ unsigned g_bar_in;
__device__ unsigned g_bar_gen;

// ---------------------------------------------------------------------------
// GEMM: C[m,n] = sum_k Arow(m)[k] * B[n,k] + bias[n]
//   Arow(m) = gather ? A + tok[m]*K : A + m*K     (both operands K-contiguous)
// Tiles: BM=128, BN=64, BK=16, 256 threads, 8x4 register tile.
// ---------------------------------------------------------------------------
__global__ void __launch_bounds__(256) gemm_tn(
    const float* __restrict__ A, const int* __restrict__ tok,
    const float* __restrict__ B, const float* __restrict__ bias,
    float* __restrict__ C, int N, int K, int gather)
{
    __shared__ float As[16][128];
    __shared__ float Bs[16][64];

    const int tid = threadIdx.x;
    const int bm = blockIdx.x * 128;
    const int bn = blockIdx.y * 64;
    const int tm0 = (tid & 15) * 8;
    const int tn0 = (tid >> 4) * 4;

    // Per-thread fixed load coordinates (hoisted)
    const int arow_i = tid >> 1;             // 0..127
    const int akq    = (tid & 1) * 2;        // kq pair {0,1} or {2,3}
    const size_t aidx = gather ? (size_t)tok[bm + arow_i] : (size_t)(bm + arow_i);
    const float* Aptr = A + aidx * (size_t)K + akq * 4;
    const int brow_i = tid >> 2;             // 0..63
    const int bkq    = tid & 3;
    const float* Bptr = B + (size_t)(bn + brow_i) * K + bkq * 4;

    float acc[8][4];
#pragma unroll
    for (int i = 0; i < 8; i++)
#pragma unroll
        for (int j = 0; j < 4; j++) acc[i][j] = 0.f;

    for (int kt = 0; kt < K; kt += 16) {
        float4 va0 = *(const float4*)(Aptr + kt);
        float4 va1 = *(const float4*)(Aptr + kt + 4);
        float4 vb  = *(const float4*)(Bptr + kt);
        __syncthreads();  // previous compute done before overwriting smem
        As[akq * 4 + 0][arow_i] = va0.x;
        As[akq * 4 + 1][arow_i] = va0.y;
        As[akq * 4 + 2][arow_i] = va0.z;
        As[akq * 4 + 3][arow_i] = va0.w;
        As[(akq + 1) * 4 + 0][arow_i] = va1.x;
        As[(akq + 1) * 4 + 1][arow_i] = va1.y;
        As[(akq + 1) * 4 + 2][arow_i] = va1.z;
        As[(akq + 1) * 4 + 3][arow_i] = va1.w;
        Bs[bkq * 4 + 0][brow_i] = vb.x;
        Bs[bkq * 4 + 1][brow_i] = vb.y;
        Bs[bkq * 4 + 2][brow_i] = vb.z;
        Bs[bkq * 4 + 3][brow_i] = vb.w;
        __syncthreads();
#pragma unroll
        for (int kk = 0; kk < 16; kk++) {
            float a[8], b[4];
#pragma unroll
            for (int i = 0; i < 8; i++) a[i] = As[kk][tm0 + i];
#pragma unroll
            for (int j = 0; j < 4; j++) b[j] = Bs[kk][tn0 + j];
#pragma unroll
            for (int i = 0; i < 8; i++)
#pragma unroll
                for (int j = 0; j < 4; j++) acc[i][j] += a[i] * b[j];
        }
    }

#pragma unroll
    for (int i = 0; i < 8; i++) {
        float4 v;
        v.x = acc[i][0] + bias[bn + tn0 + 0];
        v.y = acc[i][1] + bias[bn + tn0 + 1];
        v.z = acc[i][2] + bias[bn + tn0 + 2];
        v.w = acc[i][3] + bias[bn + tn0 + 3];
        *(float4*)(C + (size_t)(bm + tm0 + i) * N + bn + tn0) = v;
    }
}

// ---------------------------------------------------------------------------
// Persistent GRU scan. 147 CTAs; CTA owns J=7 hidden indices (21 W_hh rows
// resident in SMEM). One grid spin-barrier per time step.
// ---------------------------------------------------------------------------
#define SCAN_J 7
#define SCAN_G 147
#define SCAN_SMEM_FLOATS (3 * SCAN_J * 1024 + 16 * 1024 + 336 * 17 + 336 + 32)
#define SCAN_SMEM_BYTES  (SCAN_SMEM_FLOATS * 4)

__global__ void bar_reset() { g_bar_in = 0u; g_bar_gen = 0u; }

__global__ void __launch_bounds__(512, 1) scan_kernel(
    const float* __restrict__ gx,    // [MTOT][3H]  (gate g at offset g*1024)
    const float* __restrict__ Whh,   // [3H][H]
    const float* __restrict__ bhh,   // [3H]
    float* __restrict__ hseq)        // [MTOT][H]
{
    extern __shared__ float sm[];
    float* Ws   = sm;                      // [3*J][1024]
    float* hs   = Ws + 3 * SCAN_J * 1024;  // [16][1024]
    float* part = hs + 16 * 1024;          // [336][17]  (pad 17 vs bank conflicts)
    float* ghs  = part + 336 * 17;         // [336]
    float* bh   = ghs + 336;               // [21]

    const int tid = threadIdx.x;
    const int jbase = blockIdx.x * SCAN_J;
    const int jcnt = min(SCAN_J, 1024 - jbase);

    // Load resident W_hh rows (r/z/n gates for this CTA's j-chunk)
    for (int f = tid; f < 3 * jcnt * 256; f += 512) {
        int rl = f >> 8;
        int c4 = f & 255;
        int g  = rl / jcnt;
        int jj = rl - g * jcnt;
        float4 v = *(const float4*)(Whh + ((size_t)(g * 1024 + jbase + jj)) * 1024 + (c4 << 2));
        *(float4*)(Ws + ((g * SCAN_J + jj) << 10) + (c4 << 2)) = v;
    }
    if (tid < 3 * SCAN_J) {
        int g = tid / SCAN_J, jj = tid % SCAN_J;
        bh[tid] = (jj < jcnt) ? bhh[g * 1024 + jbase + jj] : 0.f;
    }
    __syncthreads();

    // Compute-thread role: 448 active = 16 k-slices x 4 batch-groups x 7 j's
    int c_jj = 0, c_bg = 0, c_ks = 0;
    const bool c_act = (tid < 448);
    if (c_act) { c_jj = tid % 7; int tmp = tid / 7; c_bg = tmp & 3; c_ks = tmp >> 2; }

    unsigned gen = 0;
    for (int t = 0; t < TSEQ; t++) {
        // Stage h_{t-1} into SMEM (bypass L1: other SMs produced it)
        if (t == 0) {
            for (int f = tid; f < 4096; f += 512)
                *(float4*)(hs + (f << 2)) = make_float4(0.f, 0.f, 0.f, 0.f);
        } else {
            for (int f = tid; f < 4096; f += 512) {
                int b = f >> 8, c4 = f & 255;
                float4 v = __ldcg((const float4*)(hseq + ((size_t)(b * 1024 + (t - 1))) * 1024 + (c4 << 2)));
                *(float4*)(hs + (f << 2)) = v;
            }
        }
        __syncthreads();

        // gh partials: each thread = 3 gates x 4 batches over a 64-wide k-slice
        if (c_act) {
            const float* wr = Ws + ((0 * SCAN_J + c_jj) << 10) + (c_ks << 6);
            const float* wz = Ws + ((1 * SCAN_J + c_jj) << 10) + (c_ks << 6);
            const float* wn = Ws + ((2 * SCAN_J + c_jj) << 10) + (c_ks << 6);
            const float* hb = hs + ((c_bg * 4) << 10) + (c_ks << 6);
            float acc[3][4];
#pragma unroll
            for (int g = 0; g < 3; g++)
#pragma unroll
                for (int q = 0; q < 4; q++) acc[g][q] = 0.f;

#pragma unroll 4
            for (int k4 = 0; k4 < 16; k4++) {
                float4 w0 = *(const float4*)(wr + (k4 << 2));
                float4 w1 = *(const float4*)(wz + (k4 << 2));
                float4 w2 = *(const float4*)(wn + (k4 << 2));
                float4 h0 = *(const float4*)(hb + (k4 << 2));
                float4 h1 = *(const float4*)(hb + 1024 + (k4 << 2));
                float4 h2 = *(const float4*)(hb + 2048 + (k4 << 2));
                float4 h3 = *(const float4*)(hb + 3072 + (k4 << 2));
                float4 wv[3] = {w0, w1, w2};
                float4 hv[4] = {h0, h1, h2, h3};
#pragma unroll
                for (int g = 0; g < 3; g++)
#pragma unroll
                    for (int q = 0; q < 4; q++) {
                        acc[g][q] = fmaf(wv[g].x, hv[q].x, acc[g][q]);
                        acc[g][q] = fmaf(wv[g].y, hv[q].y, acc[g][q]);
                        acc[g][q] = fmaf(wv[g].z, hv[q].z, acc[g][q]);
                        acc[g][q] = fmaf(wv[g].w, hv[q].w, acc[g][q]);
                    }
            }
#pragma unroll
            for (int g = 0; g < 3; g++)
#pragma unroll
                for (int q = 0; q < 4; q++) {
                    int b = c_bg * 4 + q;
                    part[(b * 21 + g * 7 + c_jj) * 17 + c_ks] = acc[g][q];
                }
        }
        __syncthreads();

        // Reduce 16 k-slice partials -> gh (+ b_hh)
        if (tid < 336) {
            float s = 0.f;
#pragma unroll
            for (int ks = 0; ks < 16; ks++) s += part[tid * 17 + ks];
            ghs[tid] = s + bh[tid % 21];
        }
        __syncthreads();

        // Gate math + write h_t (this CTA's j-chunk only)
        if (tid < 112) {
            int jj = tid % 7;
            int b  = tid / 7;
            if (jj < jcnt) {
                size_t mrow = (size_t)(b * 1024 + t);
                const float* gxp = gx + mrow * 3072 + jbase + jj;
                float xr = gxp[0], xz = gxp[1024], xn = gxp[2048];
                float ghr = ghs[b * 21 + jj];
                float ghz = ghs[b * 21 + 7 + jj];
                float ghn = ghs[b * 21 + 14 + jj];
                float r = 1.f / (1.f + expf(-(xr + ghr)));
                float z = 1.f / (1.f + expf(-(xz + ghz)));
                float n = tanhf(xn + r * ghn);
                float hp = hs[(b << 10) + jbase + jj];
                __stcg(hseq + mrow * 1024 + jbase + jj, (1.f - z) * n + z * hp);
            }
        }

        // Grid barrier (release writes -> arrive -> acquire)
        gen++;
        __threadfence();
        __syncthreads();
        if (tid == 0) {
            unsigned arr = atomicAdd(&g_bar_in, 1u);
            if (arr == (unsigned)SCAN_G * gen - 1u) {
                atomicExch(&g_bar_gen, gen);
            } else {
                while (atomicAdd(&g_bar_gen, 0u) < gen) __nanosleep(64);
            }
            __threadfence();
        }
        __syncthreads();
    }
}

// ---------------------------------------------------------------------------
// log_softmax over axis=1 (the T axis): out[b,t,c] = logits - lse[b,c]
// ---------------------------------------------------------------------------
__global__ void lse_kernel(const float* __restrict__ logits, float* __restrict__ lse)
{
    int b = blockIdx.x, c = threadIdx.x;
    const float* p = logits + (size_t)b * TSEQ * NCLS + c;
    float m = -1e30f, s = 0.f;
    for (int t = 0; t < TSEQ; t++) {
        float x = p[(size_t)t * NCLS];
        if (x > m) { s = s * expf(m - x) + 1.f; m = x; }
        else       { s += expf(x - m); }
    }
    lse[b * NCLS + c] = m + logf(s);
}

__global__ void sub_kernel(float* __restrict__ out, const float* __restrict__ lse)
{
    int idx = blockIdx.x * blockDim.x + threadIdx.x;   // < 2097152
    int b = idx >> 17;        // / (1024*128)
    int c = idx & 127;
    out[idx] -= lse[(b << 7) + c];
}

// ---------------------------------------------------------------------------
extern "C" void kernel_launch(void* const* d_in, const int* in_sizes, int n_in,
                              void* d_out, int out_size)
{
    (void)in_sizes; (void)n_in; (void)out_size;
    const int*   tok  = (const int*)d_in[0];
    const float* emb  = (const float*)d_in[1];
    const float* Wih0 = (const float*)d_in[2];
    const float* Whh0 = (const float*)d_in[3];
    const float* bih0 = (const float*)d_in[4];
    const float* bhh0 = (const float*)d_in[5];
    const float* Wih1 = (const float*)d_in[6];
    const float* Whh1 = (const float*)d_in[7];
    const float* bih1 = (const float*)d_in[8];
    const float* bhh1 = (const float*)d_in[9];
    const float* Wlin = (const float*)d_in[10];
    const float* blin = (const float*)d_in[11];
    float* out = (float*)d_out;

    float *gx, *hseq, *lseb;
    cudaGetSymbolAddress((void**)&gx,   g_gx);
    cudaGetSymbolAddress((void**)&hseq, g_hseq);
    cudaGetSymbolAddress((void**)&lseb, g_lse);

    cudaFuncSetAttribute(scan_kernel, cudaFuncAttributeMaxDynamicSharedMemorySize,
                         SCAN_SMEM_BYTES);

    dim3 gA(MTOT / 128, G3H / 64);   // (128, 48)
    // Layer 0
    gemm_tn<<<gA, 256>>>(emb, tok, Wih0, bih0, gx, G3H, HD, 1);
    bar_reset<<<1, 1>>>();
    scan_kernel<<<SCAN_G, 512, SCAN_SMEM_BYTES>>>(gx, Whh0, bhh0, hseq);
    // Layer 1
    gemm_tn<<<gA, 256>>>(hseq, nullptr, Wih1, bih1, gx, G3H, HD, 0);
    bar_reset<<<1, 1>>>();
    scan_kernel<<<SCAN_G, 512, SCAN_SMEM_BYTES>>>(gx, Whh1, bhh1, hseq);
    // Head
    dim3 gL(MTOT / 128, NCLS / 64);  // (128, 2)
    gemm_tn<<<gL, 256>>>(hseq, nullptr, Wlin, blin, out, NCLS, HD, 0);
    // log_softmax over T
    lse_kernel<<<BATCH, NCLS>>>(out, lseb);
    sub_kernel<<<(MTOT * NCLS) / 1024, 1024>>>(out, lseb);
}

// round 3
// speedup vs baseline: 2.2225x; 2.2225x over previous
#include <cuda_runtime.h>
#include <math.h>

#define BATCH 16
#define TSEQ  1024
#define HD    1024
#define MTOT  (BATCH * TSEQ)   // 16384
#define G3H   (3 * HD)         // 3072
#define NCLS  128

__device__ float g_gx[(size_t)MTOT * G3H];     // 192 MB
__device__ float g_hseq[(size_t)MTOT * HD];    // 64 MB
__device__ float g_lse[BATCH * NCLS];
__device__ unsigned g_bar_in;
__device__ unsigned g_bar_gen;

// ---------------------------------------------------------------------------
// GEMM: C[m,n] = sum_k Arow(m)[k] * B[n,k] + bias[n]
// 128x128x16 tile, 256 threads, 8x8 register tile (4+4 split, conflict-free).
// ---------------------------------------------------------------------------
__global__ void __launch_bounds__(256) gemm_tn(
    const float* __restrict__ A, const int* __restrict__ tok,
    const float* __restrict__ B, const float* __restrict__ bias,
    float* __restrict__ C, int N, int K, int gather)
{
    __shared__ float As[16 * 132];
    __shared__ float Bs[16 * 132];

    const int tid = threadIdx.x;
    const int bm = blockIdx.x * 128;
    const int bn = blockIdx.y * 128;
    const int m0 = (tid & 15) * 4;         // rows m0..m0+3 and m0+64..m0+67
    const int n0 = (tid >> 4) * 4;         // cols n0..n0+3 and n0+64..n0+67

    const int lrow = tid >> 1;             // 0..127
    const int lk   = (tid & 1) * 8;        // k offset 0 or 8
    const size_t aidx = gather ? (size_t)tok[bm + lrow] : (size_t)(bm + lrow);
    const float* Ap = A + aidx * (size_t)K + lk;
    const float* Bp = B + (size_t)(bn + lrow) * K + lk;

    float acc[8][8];
#pragma unroll
    for (int i = 0; i < 8; i++)
#pragma unroll
        for (int j = 0; j < 8; j++) acc[i][j] = 0.f;

    for (int kt = 0; kt < K; kt += 16) {
        float4 a0 = *(const float4*)(Ap + kt);
        float4 a1 = *(const float4*)(Ap + kt + 4);
        float4 b0 = *(const float4*)(Bp + kt);
        float4 b1 = *(const float4*)(Bp + kt + 4);
        __syncthreads();
        As[(lk + 0) * 132 + lrow] = a0.x;
        As[(lk + 1) * 132 + lrow] = a0.y;
        As[(lk + 2) * 132 + lrow] = a0.z;
        As[(lk + 3) * 132 + lrow] = a0.w;
        As[(lk + 4) * 132 + lrow] = a1.x;
        As[(lk + 5) * 132 + lrow] = a1.y;
        As[(lk + 6) * 132 + lrow] = a1.z;
        As[(lk + 7) * 132 + lrow] = a1.w;
        Bs[(lk + 0) * 132 + lrow] = b0.x;
        Bs[(lk + 1) * 132 + lrow] = b0.y;
        Bs[(lk + 2) * 132 + lrow] = b0.z;
        Bs[(lk + 3) * 132 + lrow] = b0.w;
        Bs[(lk + 4) * 132 + lrow] = b1.x;
        Bs[(lk + 5) * 132 + lrow] = b1.y;
        Bs[(lk + 6) * 132 + lrow] = b1.z;
        Bs[(lk + 7) * 132 + lrow] = b1.w;
        __syncthreads();
#pragma unroll
        for (int kk = 0; kk < 16; kk++) {
            float4 av0 = *(const float4*)(As + kk * 132 + m0);
            float4 av1 = *(const float4*)(As + kk * 132 + m0 + 64);
            float4 bv0 = *(const float4*)(Bs + kk * 132 + n0);
            float4 bv1 = *(const float4*)(Bs + kk * 132 + n0 + 64);
            float a[8] = {av0.x, av0.y, av0.z, av0.w, av1.x, av1.y, av1.z, av1.w};
            float b[8] = {bv0.x, bv0.y, bv0.z, bv0.w, bv1.x, bv1.y, bv1.z, bv1.w};
#pragma unroll
            for (int i = 0; i < 8; i++)
#pragma unroll
                for (int j = 0; j < 8; j++) acc[i][j] = fmaf(a[i], b[j], acc[i][j]);
        }
    }

#pragma unroll
    for (int ih = 0; ih < 2; ih++)
#pragma unroll
        for (int i = 0; i < 4; i++) {
            const int r = bm + m0 + ih * 64 + i;
#pragma unroll
            for (int jh = 0; jh < 2; jh++) {
                const int cb = bn + n0 + jh * 64;
                float4 v;
                v.x = acc[ih * 4 + i][jh * 4 + 0] + bias[cb + 0];
                v.y = acc[ih * 4 + i][jh * 4 + 1] + bias[cb + 1];
                v.z = acc[ih * 4 + i][jh * 4 + 2] + bias[cb + 2];
                v.w = acc[ih * 4 + i][jh * 4 + 3] + bias[cb + 3];
                *(float4*)(C + (size_t)r * N + cb) = v;
            }
        }
}

// ---------------------------------------------------------------------------
// Persistent GRU scan. 128 CTAs x 256 threads; CTA owns J=8 hidden indices
// (24 W_hh rows in SMEM, row stride 1028 -> conflict-free). Thread tile:
// 3 gates x 16 batches over a 32-wide k-slice. Lane map tid = ks*8 + jj ->
// h loads are warp-phase broadcasts; W loads hit banks 4*jj (conflict-free).
// ---------------------------------------------------------------------------
#define SCAN_J 8
#define SCAN_G 128
#define WSTR 1028
#define PSTR 516
// floats: W 24*1028 + h 16*1024 + part 24*516 + ghs 384 + bh 24
#define SCAN_SMEM_FLOATS (24 * WSTR + 16 * 1024 + 24 * PSTR + 384 + 24)
#define SCAN_SMEM_BYTES  (SCAN_SMEM_FLOATS * 4)

__global__ void bar_reset() { g_bar_in = 0u; g_bar_gen = 0u; }

__global__ void __launch_bounds__(256, 1) scan_kernel(
    const float* __restrict__ gx,    // [MTOT][3H]
    const float* __restrict__ Whh,   // [3H][H]
    const float* __restrict__ bhh,   // [3H]
    float* __restrict__ hseq)        // [MTOT][H]
{
    extern __shared__ float sm[];
    float* Ws   = sm;                      // [24][1028]
    float* hs   = Ws + 24 * WSTR;          // [16][1024]
    float* part = hs + 16 * 1024;          // [24][516] : r*516 + ks*16 + b
    float* ghs  = part + 24 * PSTR;        // [384] : r*16 + b
    float* bh   = ghs + 384;               // [24]

    const int tid = threadIdx.x;
    const int jbase = blockIdx.x * SCAN_J;

    // Load resident W_hh rows: row r = g*8 + jj  <-  Whh[g*1024 + jbase + jj]
    for (int f = tid; f < 24 * 256; f += 256) {
        int r = f >> 8, c4 = f & 255;
        int g = r >> 3, jj = r & 7;
        float4 v = *(const float4*)(Whh + ((size_t)(g * 1024 + jbase + jj)) * 1024 + (c4 << 2));
        *(float4*)(Ws + r * WSTR + (c4 << 2)) = v;
    }
    if (tid < 24) bh[tid] = bhh[(tid >> 3) * 1024 + jbase + (tid & 7)];
    __syncthreads();

    const int c_jj = tid & 7;
    const int c_ks = tid >> 3;    // 0..31
    const float* wR = Ws + c_jj * WSTR + (c_ks << 5);
    const float* wZ = wR + 8 * WSTR;
    const float* wN = wR + 16 * WSTR;
    const float* hp = hs + (c_ks << 5);
    float* pp = part + c_jj * PSTR + (c_ks << 4);   // + g*8*PSTR + q

    unsigned gen = 0;
    for (int t = 0; t < TSEQ; t++) {
        // Stage h_{t-1} into SMEM
        if (t == 0) {
            for (int f = tid; f < 4096; f += 256)
                *(float4*)(hs + (f << 2)) = make_float4(0.f, 0.f, 0.f, 0.f);
        } else {
            for (int f = tid; f < 4096; f += 256) {
                int b = f >> 8, c4 = f & 255;
                float4 v = __ldcg((const float4*)(hseq + ((size_t)((b << 10) + (t - 1))) * 1024 + (c4 << 2)));
                *(float4*)(hs + (b << 10) + (c4 << 2)) = v;
            }
        }
        __syncthreads();

        // Main: 3 gates x 16 batches, 32-wide k-slice
        float acc[3][16];
#pragma unroll
        for (int g = 0; g < 3; g++)
#pragma unroll
            for (int q = 0; q < 16; q++) acc[g][q] = 0.f;

#pragma unroll
        for (int k4 = 0; k4 < 8; k4++) {
            float4 wr = *(const float4*)(wR + (k4 << 2));
            float4 wz = *(const float4*)(wZ + (k4 << 2));
            float4 wn = *(const float4*)(wN + (k4 << 2));
#pragma unroll
            for (int q = 0; q < 16; q++) {
                float4 h = *(const float4*)(hp + (q << 10) + (k4 << 2));
                acc[0][q] = fmaf(wr.x, h.x, fmaf(wr.y, h.y, fmaf(wr.z, h.z, fmaf(wr.w, h.w, acc[0][q]))));
                acc[1][q] = fmaf(wz.x, h.x, fmaf(wz.y, h.y, fmaf(wz.z, h.z, fmaf(wz.w, h.w, acc[1][q]))));
                acc[2][q] = fmaf(wn.x, h.x, fmaf(wn.y, h.y, fmaf(wn.z, h.z, fmaf(wn.w, h.w, acc[2][q]))));
            }
        }

        // Write partials (float4, conflict-free via 516 stride)
#pragma unroll
        for (int g = 0; g < 3; g++)
#pragma unroll
            for (int q0 = 0; q0 < 16; q0 += 4) {
                float4 v = make_float4(acc[g][q0], acc[g][q0 + 1], acc[g][q0 + 2], acc[g][q0 + 3]);
                *(float4*)(pp + g * 8 * PSTR + q0) = v;
            }
        __syncthreads();

        // Reduce 32 k-slice partials -> ghs (+ b_hh). 384 outputs.
        {
            int o = tid;
            int r = o >> 4, b = o & 15;
            float s = 0.f;
#pragma unroll
            for (int ks = 0; ks < 32; ks++) s += part[r * PSTR + (ks << 4) + b];
            ghs[o] = s + bh[r];
            if (tid < 128) {
                o = 256 + tid;
                r = o >> 4; b = o & 15;
                s = 0.f;
#pragma unroll
                for (int ks = 0; ks < 32; ks++) s += part[r * PSTR + (ks << 4) + b];
                ghs[o] = s + bh[r];
            }
        }
        __syncthreads();

        // Gate math + write h_t (128 outputs: 16 b x 8 jj)
        if (tid < 128) {
            int jj = tid & 7;
            int b  = tid >> 3;
            size_t mrow = (size_t)((b << 10) + t);
            const float* gxp = gx + mrow * 3072 + jbase + jj;
            float xr = gxp[0], xz = gxp[1024], xn = gxp[2048];
            float ghr = ghs[jj * 16 + b];
            float ghz = ghs[(8 + jj) * 16 + b];
            float ghn = ghs[(16 + jj) * 16 + b];
            float rg = 1.f / (1.f + expf(-(xr + ghr)));
            float zg = 1.f / (1.f + expf(-(xz + ghz)));
            float ng = tanhf(xn + rg * ghn);
            float hprev = hs[(b << 10) + jbase + jj];
            __stcg(hseq + mrow * 1024 + jbase + jj, (1.f - zg) * ng + zg * hprev);
        }

        // Grid barrier
        gen++;
        __threadfence();
        __syncthreads();
        if (tid == 0) {
            unsigned arr = atomicAdd(&g_bar_in, 1u);
            if (arr == (unsigned)SCAN_G * gen - 1u) {
                atomicExch(&g_bar_gen, gen);
            } else {
                while (atomicAdd(&g_bar_gen, 0u) < gen) __nanosleep(32);
            }
            __threadfence();
        }
        __syncthreads();
    }
}

// ---------------------------------------------------------------------------
// log_softmax over axis=1 (T). One block per batch; lanes are class-contiguous.
// ---------------------------------------------------------------------------
__global__ void __launch_bounds__(1024) lse_kernel(
    const float* __restrict__ logits, float* __restrict__ lse)
{
    __shared__ float sm_m[1024], sm_s[1024];
    const int b = blockIdx.x;
    const int tid = threadIdx.x;
    const int c = tid & 127, ts = tid >> 7;   // 8 t-slices of 128
    const float* p = logits + ((size_t)((b << 10) + (ts << 7))) * NCLS + c;
    float m = -1e30f, s = 0.f;
    for (int i = 0; i < 128; i++) {
        float x = p[(size_t)i * NCLS];
        if (x > m) { s = s * expf(m - x) + 1.f; m = x; }
        else       { s += expf(x - m); }
    }
    sm_m[tid] = m; sm_s[tid] = s;
    __syncthreads();
    if (tid < 128) {
        float M = sm_m[tid], S = sm_s[tid];
#pragma unroll
        for (int k = 1; k < 8; k++) {
            float m2 = sm_m[tid + k * 128], s2 = sm_s[tid + k * 128];
            if (m2 > M) { S = S * expf(M - m2) + s2; M = m2; }
            else        { S += s2 * expf(m2 - M); }
        }
        lse[b * NCLS + tid] = M + logf(S);
    }
}

__global__ void sub_kernel(float* __restrict__ out, const float* __restrict__ lse)
{
    int idx = blockIdx.x * blockDim.x + threadIdx.x;   // < 2097152
    int b = idx >> 17;
    int c = idx & 127;
    out[idx] -= lse[(b << 7) + c];
}

// ---------------------------------------------------------------------------
extern "C" void kernel_launch(void* const* d_in, const int* in_sizes, int n_in,
                              void* d_out, int out_size)
{
    (void)in_sizes; (void)n_in; (void)out_size;
    const int*   tok  = (const int*)d_in[0];
    const float* emb  = (const float*)d_in[1];
    const float* Wih0 = (const float*)d_in[2];
    const float* Whh0 = (const float*)d_in[3];
    const float* bih0 = (const float*)d_in[4];
    const float* bhh0 = (const float*)d_in[5];
    const float* Wih1 = (const float*)d_in[6];
    const float* Whh1 = (const float*)d_in[7];
    const float* bih1 = (const float*)d_in[8];
    const float* bhh1 = (const float*)d_in[9];
    const float* Wlin = (const float*)d_in[10];
    const float* blin = (const float*)d_in[11];
    float* out = (float*)d_out;

    float *gx, *hseq, *lseb;
    cudaGetSymbolAddress((void**)&gx,   g_gx);
    cudaGetSymbolAddress((void**)&hseq, g_hseq);
    cudaGetSymbolAddress((void**)&lseb, g_lse);

    cudaFuncSetAttribute(scan_kernel, cudaFuncAttributeMaxDynamicSharedMemorySize,
                         SCAN_SMEM_BYTES);

    dim3 gA(MTOT / 128, G3H / 128);   // (128, 24)
    // Layer 0
    gemm_tn<<<gA, 256>>>(emb, tok, Wih0, bih0, gx, G3H, HD, 1);
    bar_reset<<<1, 1>>>();
    scan_kernel<<<SCAN_G, 256, SCAN_SMEM_BYTES>>>(gx, Whh0, bhh0, hseq);
    // Layer 1
    gemm_tn<<<gA, 256>>>(hseq, nullptr, Wih1, bih1, gx, G3H, HD, 0);
    bar_reset<<<1, 1>>>();
    scan_kernel<<<SCAN_G, 256, SCAN_SMEM_BYTES>>>(gx, Whh1, bhh1, hseq);
    // Head
    dim3 gL(MTOT / 128, 1);
    gemm_tn<<<gL, 256>>>(hseq, nullptr, Wlin, blin, out, NCLS, HD, 0);
    // log_softmax over T
    lse_kernel<<<BATCH, 1024>>>(out, lseb);
    sub_kernel<<<(MTOT * NCLS) / 1024, 1024>>>(out, lseb);
}

// round 5
// speedup vs baseline: 2.3289x; 1.0479x over previous
#include <cuda_runtime.h>
#include <cstdint>
#include <math.h>

#define BATCH 16
#define TSEQ  1024
#define HD    1024
#define MTOT  (BATCH * TSEQ)   // 16384
#define G3H   (3 * HD)         // 3072
#define NCLS  128

__device__ float g_gx[(size_t)MTOT * G3H];     // 192 MB
__device__ float g_hseq[(size_t)MTOT * HD];    // 64 MB
__device__ float g_lse[BATCH * NCLS];
__device__ unsigned g_bar_in;
__device__ unsigned g_bar_gen;

// ---------------------------------------------------------------------------
// tf32 tensor-core GEMM: C[m,n] = sum_k Arow(m)[k] * B[n,k] + bias[n]
// CTA tile 128x128x32, 8 warps (2x4), warp tile 64x32, mma.m16n8k8.tf32.
// ---------------------------------------------------------------------------
__device__ __forceinline__ uint32_t f2tf(float x) {
    uint32_t r;
    asm("cvt.rna.tf32.f32 %0, %1;" : "=r"(r) : "f"(x));
    return r;
}

__device__ __forceinline__ void mma8(float* d, const uint32_t* a, const uint32_t* b) {
    asm volatile(
        "mma.sync.aligned.m16n8k8.row.col.f32.tf32.tf32.f32 "
        "{%0,%1,%2,%3}, {%4,%5,%6,%7}, {%8,%9}, {%0,%1,%2,%3};"
        : "+f"(d[0]), "+f"(d[1]), "+f"(d[2]), "+f"(d[3])
        : "r"(a[0]), "r"(a[1]), "r"(a[2]), "r"(a[3]), "r"(b[0]), "r"(b[1]));
}

#define SSTR 132

__global__ void __launch_bounds__(256) gemm_tf32(
    const float* __restrict__ A, const int* __restrict__ tok,
    const float* __restrict__ B, const float* __restrict__ bias,
    float* __restrict__ C, int N, int K, int gather)
{
    __shared__ float As[32 * SSTR];   // [k][m], k-major
    __shared__ float Bs[32 * SSTR];   // [k][n]

    const int tid  = threadIdx.x;
    const int lane = tid & 31;
    const int warp = tid >> 5;
    const int bm = blockIdx.x * 128;
    const int bn = blockIdx.y * 128;
    const int wm = (warp & 1) * 64;
    const int wn = (warp >> 1) * 32;
    const int qr = lane >> 2;          // 0..7
    const int qc = lane & 3;           // 0..3

    // Global-load role: 128 rows x 2 k-halves of 16
    const int ml = tid & 127;
    const int kh = (tid >> 7) * 16;
    const size_t aidx = gather ? (size_t)tok[bm + ml] : (size_t)(bm + ml);
    const float* Ap = A + aidx * (size_t)K + kh;
    const float* Bp = B + (size_t)(bn + ml) * K + kh;

    float acc[4][4][4];
#pragma unroll
    for (int mf = 0; mf < 4; mf++)
#pragma unroll
        for (int nf = 0; nf < 4; nf++)
#pragma unroll
            for (int i = 0; i < 4; i++) acc[mf][nf][i] = 0.f;

    float4 ra[4], rb[4];
#pragma unroll
    for (int j = 0; j < 4; j++) {
        ra[j] = *(const float4*)(Ap + j * 4);
        rb[j] = *(const float4*)(Bp + j * 4);
    }

    for (int kt = 0; kt < K; kt += 32) {
        __syncthreads();
        // Store staged tile to smem (transpose to k-major, tf32-round).
        // Lanes have consecutive ml, same k row -> conflict-free.
#pragma unroll
        for (int j = 0; j < 4; j++) {
            const int kr = kh + j * 4;
            As[(kr + 0) * SSTR + ml] = __uint_as_float(f2tf(ra[j].x));
            As[(kr + 1) * SSTR + ml] = __uint_as_float(f2tf(ra[j].y));
            As[(kr + 2) * SSTR + ml] = __uint_as_float(f2tf(ra[j].z));
            As[(kr + 3) * SSTR + ml] = __uint_as_float(f2tf(ra[j].w));
            Bs[(kr + 0) * SSTR + ml] = __uint_as_float(f2tf(rb[j].x));
            Bs[(kr + 1) * SSTR + ml] = __uint_as_float(f2tf(rb[j].y));
            Bs[(kr + 2) * SSTR + ml] = __uint_as_float(f2tf(rb[j].z));
            Bs[(kr + 3) * SSTR + ml] = __uint_as_float(f2tf(rb[j].w));
        }
        __syncthreads();

        // Prefetch next tile while computing this one
        if (kt + 32 < K) {
#pragma unroll
            for (int j = 0; j < 4; j++) {
                ra[j] = *(const float4*)(Ap + kt + 32 + j * 4);
                rb[j] = *(const float4*)(Bp + kt + 32 + j * 4);
            }
        }

#pragma unroll
        for (int kk = 0; kk < 4; kk++) {
            const int k8 = kk * 8;
            uint32_t af[4][4], bf[4][2];
#pragma unroll
            for (int mf = 0; mf < 4; mf++) {
                const int r = wm + mf * 16 + qr;
                af[mf][0] = __float_as_uint(As[(k8 + qc) * SSTR + r]);
                af[mf][1] = __float_as_uint(As[(k8 + qc) * SSTR + r + 8]);
                af[mf][2] = __float_as_uint(As[(k8 + 4 + qc) * SSTR + r]);
                af[mf][3] = __float_as_uint(As[(k8 + 4 + qc) * SSTR + r + 8]);
            }
#pragma unroll
            for (int nf = 0; nf < 4; nf++) {
                const int c = wn + nf * 8 + qr;
                bf[nf][0] = __float_as_uint(Bs[(k8 + qc) * SSTR + c]);
                bf[nf][1] = __float_as_uint(Bs[(k8 + 4 + qc) * SSTR + c]);
            }
#pragma unroll
            for (int mf = 0; mf < 4; mf++)
#pragma unroll
                for (int nf = 0; nf < 4; nf++)
                    mma8(acc[mf][nf], af[mf], bf[nf]);
        }
    }

    // Epilogue: bias + store (c0,c1)/(c2,c3) as float2
#pragma unroll
    for (int nf = 0; nf < 4; nf++) {
        const int c = bn + wn + nf * 8 + 2 * qc;
        const float b0 = bias[c], b1 = bias[c + 1];
#pragma unroll
        for (int mf = 0; mf < 4; mf++) {
            const int r0 = bm + wm + mf * 16 + qr;
            float2 v0 = make_float2(acc[mf][nf][0] + b0, acc[mf][nf][1] + b1);
            float2 v1 = make_float2(acc[mf][nf][2] + b0, acc[mf][nf][3] + b1);
            *(float2*)(C + (size_t)r0 * N + c) = v0;
            *(float2*)(C + (size_t)(r0 + 8) * N + c) = v1;
        }
    }
}

// ---------------------------------------------------------------------------
// Persistent GRU scan (unchanged — near fp32 floor; next round's target).
// ---------------------------------------------------------------------------
#define SCAN_J 8
#define SCAN_G 128
#define WSTR 1028
#define PSTR 516
#define SCAN_SMEM_FLOATS (24 * WSTR + 16 * 1024 + 24 * PSTR + 384 + 24)
#define SCAN_SMEM_BYTES  (SCAN_SMEM_FLOATS * 4)

__global__ void bar_reset() { g_bar_in = 0u; g_bar_gen = 0u; }

__global__ void __launch_bounds__(256, 1) scan_kernel(
    const float* __restrict__ gx,
    const float* __restrict__ Whh,
    const float* __restrict__ bhh,
    float* __restrict__ hseq)
{
    extern __shared__ float sm[];
    float* Ws   = sm;                      // [24][1028]
    float* hs   = Ws + 24 * WSTR;          // [16][1024]
    float* part = hs + 16 * 1024;          // [24][516]
    float* ghs  = part + 24 * PSTR;        // [384]
    float* bh   = ghs + 384;               // [24]

    const int tid = threadIdx.x;
    const int jbase = blockIdx.x * SCAN_J;

    for (int f = tid; f < 24 * 256; f += 256) {
        int r = f >> 8, c4 = f & 255;
        int g = r >> 3, jj = r & 7;
        float4 v = *(const float4*)(Whh + ((size_t)(g * 1024 + jbase + jj)) * 1024 + (c4 << 2));
        *(float4*)(Ws + r * WSTR + (c4 << 2)) = v;
    }
    if (tid < 24) bh[tid] = bhh[(tid >> 3) * 1024 + jbase + (tid & 7)];
    __syncthreads();

    const int c_jj = tid & 7;
    const int c_ks = tid >> 3;
    const float* wR = Ws + c_jj * WSTR + (c_ks << 5);
    const float* wZ = wR + 8 * WSTR;
    const float* wN = wR + 16 * WSTR;
    const float* hp = hs + (c_ks << 5);
    float* pp = part + c_jj * PSTR + (c_ks << 4);

    unsigned gen = 0;
    for (int t = 0; t < TSEQ; t++) {
        if (t == 0) {
            for (int f = tid; f < 4096; f += 256)
                *(float4*)(hs + (f << 2)) = make_float4(0.f, 0.f, 0.f, 0.f);
        } else {
            for (int f = tid; f < 4096; f += 256) {
                int b = f >> 8, c4 = f & 255;
                float4 v = __ldcg((const float4*)(hseq + ((size_t)((b << 10) + (t - 1))) * 1024 + (c4 << 2)));
                *(float4*)(hs + (b << 10) + (c4 << 2)) = v;
            }
        }
        __syncthreads();

        float acc[3][16];
#pragma unroll
        for (int g = 0; g < 3; g++)
#pragma unroll
            for (int q = 0; q < 16; q++) acc[g][q] = 0.f;

#pragma unroll
        for (int k4 = 0; k4 < 8; k4++) {
            float4 wr = *(const float4*)(wR + (k4 << 2));
            float4 wz = *(const float4*)(wZ + (k4 << 2));
            float4 wn = *(const float4*)(wN + (k4 << 2));
#pragma unroll
            for (int q = 0; q < 16; q++) {
                float4 h = *(const float4*)(hp + (q << 10) + (k4 << 2));
                acc[0][q] = fmaf(wr.x, h.x, fmaf(wr.y, h.y, fmaf(wr.z, h.z, fmaf(wr.w, h.w, acc[0][q]))));
                acc[1][q] = fmaf(wz.x, h.x, fmaf(wz.y, h.y, fmaf(wz.z, h.z, fmaf(wz.w, h.w, acc[1][q]))));
                acc[2][q] = fmaf(wn.x, h.x, fmaf(wn.y, h.y, fmaf(wn.z, h.z, fmaf(wn.w, h.w, acc[2][q]))));
            }
        }

#pragma unroll
        for (int g = 0; g < 3; g++)
#pragma unroll
            for (int q0 = 0; q0 < 16; q0 += 4) {
                float4 v = make_float4(acc[g][q0], acc[g][q0 + 1], acc[g][q0 + 2], acc[g][q0 + 3]);
                *(float4*)(pp + g * 8 * PSTR + q0) = v;
            }
        __syncthreads();

        {
            int o = tid;
            int r = o >> 4, b = o & 15;
            float s = 0.f;
#pragma unroll
            for (int ks = 0; ks < 32; ks++) s += part[r * PSTR + (ks << 4) + b];
            ghs[o] = s + bh[r];
            if (tid < 128) {
                o = 256 + tid;
                r = o >> 4; b = o & 15;
                s = 0.f;
#pragma unroll
                for (int ks = 0; ks < 32; ks++) s += part[r * PSTR + (ks << 4) + b];
                ghs[o] = s + bh[r];
            }
        }
        __syncthreads();

        if (tid < 128) {
            int jj = tid & 7;
            int b  = tid >> 3;
            size_t mrow = (size_t)((b << 10) + t);
            const float* gxp = gx + mrow * 3072 + jbase + jj;
            float xr = gxp[0], xz = gxp[1024], xn = gxp[2048];
            float ghr = ghs[jj * 16 + b];
            float ghz = ghs[(8 + jj) * 16 + b];
            float ghn = ghs[(16 + jj) * 16 + b];
            float rg = 1.f / (1.f + expf(-(xr + ghr)));
            float zg = 1.f / (1.f + expf(-(xz + ghz)));
            float ng = tanhf(xn + rg * ghn);
            float hprev = hs[(b << 10) + jbase + jj];
            __stcg(hseq + mrow * 1024 + jbase + jj, (1.f - zg) * ng + zg * hprev);
        }

        gen++;
        __threadfence();
        __syncthreads();
        if (tid == 0) {
            unsigned arr = atomicAdd(&g_bar_in, 1u);
            if (arr == (unsigned)SCAN_G * gen - 1u) {
                atomicExch(&g_bar_gen, gen);
            } else {
                while (atomicAdd(&g_bar_gen, 0u) < gen) __nanosleep(32);
            }
            __threadfence();
        }
        __syncthreads();
    }
}

// ---------------------------------------------------------------------------
// log_softmax over axis=1 (T)
// ---------------------------------------------------------------------------
__global__ void __launch_bounds__(1024) lse_kernel(
    const float* __restrict__ logits, float* __restrict__ lse)
{
    __shared__ float sm_m[1024], sm_s[1024];
    const int b = blockIdx.x;
    const int tid = threadIdx.x;
    const int c = tid & 127, ts = tid >> 7;
    const float* p = logits + ((size_t)((b << 10) + (ts << 7))) * NCLS + c;
    float m = -1e30f, s = 0.f;
    for (int i = 0; i < 128; i++) {
        float x = p[(size_t)i * NCLS];
        if (x > m) { s = s * expf(m - x) + 1.f; m = x; }
        else       { s += expf(x - m); }
    }
    sm_m[tid] = m; sm_s[tid] = s;
    __syncthreads();
    if (tid < 128) {
        float M = sm_m[tid], S = sm_s[tid];
#pragma unroll
        for (int k = 1; k < 8; k++) {
            float m2 = sm_m[tid + k * 128], s2 = sm_s[tid + k * 128];
            if (m2 > M) { S = S * expf(M - m2) + s2; M = m2; }
            else        { S += s2 * expf(m2 - M); }
        }
        lse[b * NCLS + tid] = M + logf(S);
    }
}

__global__ void sub_kernel(float* __restrict__ out, const float* __restrict__ lse)
{
    int idx = blockIdx.x * blockDim.x + threadIdx.x;
    int b = idx >> 17;
    int c = idx & 127;
    out[idx] -= lse[(b << 7) + c];
}

// ---------------------------------------------------------------------------
extern "C" void kernel_launch(void* const* d_in, const int* in_sizes, int n_in,
                              void* d_out, int out_size)
{
    (void)in_sizes; (void)n_in; (void)out_size;
    const int*   tok  = (const int*)d_in[0];
    const float* emb  = (const float*)d_in[1];
    const float* Wih0 = (const float*)d_in[2];
    const float* Whh0 = (const float*)d_in[3];
    const float* bih0 = (const float*)d_in[4];
    const float* bhh0 = (const float*)d_in[5];
    const float* Wih1 = (const float*)d_in[6];
    const float* Whh1 = (const float*)d_in[7];
    const float* bih1 = (const float*)d_in[8];
    const float* bhh1 = (const float*)d_in[9];
    const float* Wlin = (const float*)d_in[10];
    const float* blin = (const float*)d_in[11];
    float* out = (float*)d_out;

    float *gx, *hseq, *lseb;
    cudaGetSymbolAddress((void**)&gx,   g_gx);
    cudaGetSymbolAddress((void**)&hseq, g_hseq);
    cudaGetSymbolAddress((void**)&lseb, g_lse);

    cudaFuncSetAttribute(scan_kernel, cudaFuncAttributeMaxDynamicSharedMemorySize,
                         SCAN_SMEM_BYTES);

    dim3 gA(MTOT / 128, G3H / 128);   // (128, 24)
    // Layer 0
    gemm_tf32<<<gA, 256>>>(emb, tok, Wih0, bih0, gx, G3H, HD, 1);
    bar_reset<<<1, 1>>>();
    scan_kernel<<<SCAN_G, 256, SCAN_SMEM_BYTES>>>(gx, Whh0, bhh0, hseq);
    // Layer 1
    gemm_tf32<<<gA, 256>>>(hseq, nullptr, Wih1, bih1, gx, G3H, HD, 0);
    bar_reset<<<1, 1>>>();
    scan_kernel<<<SCAN_G, 256, SCAN_SMEM_BYTES>>>(gx, Whh1, bhh1, hseq);
    // Head
    dim3 gL(MTOT / 128, 1);
    gemm_tf32<<<gL, 256>>>(hseq, nullptr, Wlin, blin, out, NCLS, HD, 0);
    // log_softmax over T
    lse_kernel<<<BATCH, 1024>>>(out, lseb);
    sub_kernel<<<(MTOT * NCLS) / 1024, 1024>>>(out, lseb);
}

// round 7
// speedup vs baseline: 2.7602x; 1.1852x over previous
#include <cuda_runtime.h>
#include <cuda_bf16.h>
#include <cstdint>
#include <math.h>

#define BATCH 16
#define TSEQ  1024
#define HD    1024
#define MTOT  (BATCH * TSEQ)   // 16384
#define G3H   (3 * HD)         // 3072
#define NCLS  128

__device__ float g_gx[(size_t)MTOT * G3H];           // 192 MB
__device__ float g_hseq[(size_t)MTOT * HD];          // 64 MB
__device__ __nv_bfloat16 g_a16[(size_t)MTOT * HD];   // 32 MB
__device__ __nv_bfloat16 g_b16[(size_t)G3H * HD];    // 6 MB
__device__ float g_lse[BATCH * NCLS];
__device__ unsigned g_bar_in;
__device__ unsigned g_bar_gen;

// ===========================================================================
// fp32 -> bf16 convert (optionally gathering rows via tok); rows are K=1024
// ===========================================================================
__global__ void __launch_bounds__(256) conv_bf16(
    const float* __restrict__ in, const int* __restrict__ tok,
    __nv_bfloat16* __restrict__ out, size_t total4)
{
    size_t idx = (size_t)blockIdx.x * blockDim.x + threadIdx.x;
    if (idx >= total4) return;
    size_t e = idx << 2;
    size_t m = e >> 10;
    int    k = (int)(e & 1023);
    size_t srow = tok ? (size_t)tok[m] : m;
    float4 v = *(const float4*)(in + srow * 1024 + k);
    __nv_bfloat162 p0 = __floats2bfloat162_rn(v.x, v.y);
    __nv_bfloat162 p1 = __floats2bfloat162_rn(v.z, v.w);
    *(__nv_bfloat162*)(out + e)     = p0;
    *(__nv_bfloat162*)(out + e + 2) = p1;
}

// ===========================================================================
// bf16 mma.sync GEMM: C[m,n] = sum_k A16[m,k]*B16[n,k] + bias[n]
// CTA 128x128, K staged 64-wide double-buffered, 8 warps (2m x 4n),
// warp tile 64x32, ldmatrix.x4 fragment loads, mma.m16n8k16.bf16, fp32 acc.
// Smem rows padded to 72 bf16 (144 B) -> all LDSM/STS phases conflict-free.
// ===========================================================================
__device__ __forceinline__ uint32_t smem_u32(const void* p) {
    uint32_t a;
    asm("{ .reg .u64 t; cvta.to.shared.u64 t, %1; cvt.u32.u64 %0, t; }"
        : "=r"(a) : "l"(p));
    return a;
}

__device__ __forceinline__ void ldsm_x4(uint32_t* r, uint32_t addr) {
    asm volatile("ldmatrix.sync.aligned.m8n8.x4.shared.b16 {%0,%1,%2,%3}, [%4];"
                 : "=r"(r[0]), "=r"(r[1]), "=r"(r[2]), "=r"(r[3]) : "r"(addr));
}

__device__ __forceinline__ void mma16(float* d, const uint32_t* a, uint32_t b0, uint32_t b1) {
    asm volatile(
        "mma.sync.aligned.m16n8k16.row.col.f32.bf16.bf16.f32 "
        "{%0,%1,%2,%3}, {%4,%5,%6,%7}, {%8,%9}, {%0,%1,%2,%3};"
        : "+f"(d[0]), "+f"(d[1]), "+f"(d[2]), "+f"(d[3])
        : "r"(a[0]), "r"(a[1]), "r"(a[2]), "r"(a[3]), "r"(b0), "r"(b1));
}

#define RSTR_B 144                        // smem row stride, bytes (72 bf16)
#define TILE_B (128 * RSTR_B)             // 18432 B per tile
#define GEMM_SMEM_BYTES (4 * TILE_B)      // A0 B0 A1 B1

__global__ void __launch_bounds__(256) gemm_bf16(
    const __nv_bfloat16* __restrict__ A16,   // [M][1024]
    const __nv_bfloat16* __restrict__ B16,   // [N][1024]
    const float* __restrict__ bias,
    float* __restrict__ C, int N)
{
    extern __shared__ char smc[];
    const uint32_t sbase = smem_u32(smc);
    const int tid  = threadIdx.x;
    const int lane = tid & 31;
    const int warp = tid >> 5;
    const int bm = blockIdx.x * 128;
    const int bn = blockIdx.y * 128;
    const int wm = (warp & 1) * 64;
    const int wn = (warp >> 1) * 32;
    const int qr = lane >> 2;
    const int qc = lane & 3;

    // Global-load role: 4 units per matrix, unit = (row, 16B chunk-of-8)
    const int r0 = tid >> 3;                 // rows r0, r0+32, r0+64, r0+96
    const int ch = tid & 7;
    const __nv_bfloat16* Ap = A16 + (size_t)(bm + r0) * 1024 + ch * 8;
    const __nv_bfloat16* Bp = B16 + (size_t)(bn + r0) * 1024 + ch * 8;
    const uint32_t s_off = (uint32_t)(r0 * RSTR_B + ch * 16);

    // Per-lane ldmatrix base addresses (within a tile)
    const uint32_t a_lm = (uint32_t)((wm + (lane & 15)) * RSTR_B + (lane >> 4) * 16);
    const uint32_t b_lm = (uint32_t)((wn + ((lane >> 4) & 1) * 8 + (lane & 7)) * RSTR_B
                                     + ((lane >> 3) & 1) * 16);

    float acc[4][4][4];
#pragma unroll
    for (int mf = 0; mf < 4; mf++)
#pragma unroll
        for (int nf = 0; nf < 4; nf++)
#pragma unroll
            for (int i = 0; i < 4; i++) acc[mf][nf][i] = 0.f;

    uint4 ra[4], rb[4];
#pragma unroll
    for (int l = 0; l < 4; l++) {
        ra[l] = *(const uint4*)(Ap + l * 32 * 1024);
        rb[l] = *(const uint4*)(Bp + l * 32 * 1024);
    }

    for (int it = 0; it < 16; it++) {
        const int buf = it & 1;
        const uint32_t abase = buf * (2 * TILE_B);
        const uint32_t bbase = abase + TILE_B;

        // Store staged K=64 chunk (prior compute on this buffer is fenced by
        // the __syncthreads inside the previous iteration)
#pragma unroll
        for (int l = 0; l < 4; l++) {
            *(uint4*)(smc + abase + s_off + l * 32 * RSTR_B) = ra[l];
            *(uint4*)(smc + bbase + s_off + l * 32 * RSTR_B) = rb[l];
        }
        __syncthreads();

        if (it + 1 < 16) {
            const size_t kofs = (size_t)(it + 1) * 64;
#pragma unroll
            for (int l = 0; l < 4; l++) {
                ra[l] = *(const uint4*)(Ap + l * 32 * 1024 + kofs);
                rb[l] = *(const uint4*)(Bp + l * 32 * 1024 + kofs);
            }
        }

        const uint32_t sA = sbase + abase + a_lm;
        const uint32_t sB = sbase + bbase + b_lm;
#pragma unroll
        for (int ks = 0; ks < 4; ks++) {
            uint32_t af[4][4], bb[2][4];
#pragma unroll
            for (int mf = 0; mf < 4; mf++)
                ldsm_x4(af[mf], sA + mf * 16 * RSTR_B + ks * 32);
#pragma unroll
            for (int np = 0; np < 2; np++)
                ldsm_x4(bb[np], sB + np * 16 * RSTR_B + ks * 32);
#pragma unroll
            for (int mf = 0; mf < 4; mf++) {
                mma16(acc[mf][0], af[mf], bb[0][0], bb[0][1]);
                mma16(acc[mf][1], af[mf], bb[0][2], bb[0][3]);
                mma16(acc[mf][2], af[mf], bb[1][0], bb[1][1]);
                mma16(acc[mf][3], af[mf], bb[1][2], bb[1][3]);
            }
        }
    }

    // Epilogue: bias + store
#pragma unroll
    for (int nf = 0; nf < 4; nf++) {
        const int c = bn + wn + nf * 8 + 2 * qc;
        const float b0 = bias[c], b1 = bias[c + 1];
#pragma unroll
        for (int mf = 0; mf < 4; mf++) {
            const int rr = bm + wm + mf * 16 + qr;
            float2 v0 = make_float2(acc[mf][nf][0] + b0, acc[mf][nf][1] + b1);
            float2 v1 = make_float2(acc[mf][nf][2] + b0, acc[mf][nf][3] + b1);
            *(float2*)(C + (size_t)rr * N + c) = v0;
            *(float2*)(C + (size_t)(rr + 8) * N + c) = v1;
        }
    }
}

// ===========================================================================
// Persistent GRU scan (unchanged)
// ===========================================================================
#define SCAN_J 8
#define SCAN_G 128
#define WSTR 1028
#define PSTR 516
#define SCAN_SMEM_FLOATS (24 * WSTR + 16 * 1024 + 24 * PSTR + 384 + 24)
#define SCAN_SMEM_BYTES  (SCAN_SMEM_FLOATS * 4)

__global__ void bar_reset() { g_bar_in = 0u; g_bar_gen = 0u; }

__global__ void __launch_bounds__(256, 1) scan_kernel(
    const float* __restrict__ gx,
    const float* __restrict__ Whh,
    const float* __restrict__ bhh,
    float* __restrict__ hseq)
{
    extern __shared__ float sm[];
    float* Ws   = sm;
    float* hs   = Ws + 24 * WSTR;
    float* part = hs + 16 * 1024;
    float* ghs  = part + 24 * PSTR;
    float* bh   = ghs + 384;

    const int tid = threadIdx.x;
    const int jbase = blockIdx.x * SCAN_J;

    for (int f = tid; f < 24 * 256; f += 256) {
        int r = f >> 8, c4 = f & 255;
        int g = r >> 3, jj = r & 7;
        float4 v = *(const float4*)(Whh + ((size_t)(g * 1024 + jbase + jj)) * 1024 + (c4 << 2));
        *(float4*)(Ws + r * WSTR + (c4 << 2)) = v;
    }
    if (tid < 24) bh[tid] = bhh[(tid >> 3) * 1024 + jbase + (tid & 7)];
    __syncthreads();

    const int c_jj = tid & 7;
    const int c_ks = tid >> 3;
    const float* wR = Ws + c_jj * WSTR + (c_ks << 5);
    const float* wZ = wR + 8 * WSTR;
    const float* wN = wR + 16 * WSTR;
    const float* hp = hs + (c_ks << 5);
    float* pp = part + c_jj * PSTR + (c_ks << 4);

    unsigned gen = 0;
    for (int t = 0; t < TSEQ; t++) {
        if (t == 0) {
            for (int f = tid; f < 4096; f += 256)
                *(float4*)(hs + (f << 2)) = make_float4(0.f, 0.f, 0.f, 0.f);
        } else {
            for (int f = tid; f < 4096; f += 256) {
                int b = f >> 8, c4 = f & 255;
                float4 v = __ldcg((const float4*)(hseq + ((size_t)((b << 10) + (t - 1))) * 1024 + (c4 << 2)));
                *(float4*)(hs + (b << 10) + (c4 << 2)) = v;
            }
        }
        __syncthreads();

        float acc[3][16];
#pragma unroll
        for (int g = 0; g < 3; g++)
#pragma unroll
            for (int q = 0; q < 16; q++) acc[g][q] = 0.f;

#pragma unroll
        for (int k4 = 0; k4 < 8; k4++) {
            float4 wr = *(const float4*)(wR + (k4 << 2));
            float4 wz = *(const float4*)(wZ + (k4 << 2));
            float4 wn = *(const float4*)(wN + (k4 << 2));
#pragma unroll
            for (int q = 0; q < 16; q++) {
                float4 h = *(const float4*)(hp + (q << 10) + (k4 << 2));
                acc[0][q] = fmaf(wr.x, h.x, fmaf(wr.y, h.y, fmaf(wr.z, h.z, fmaf(wr.w, h.w, acc[0][q]))));
                acc[1][q] = fmaf(wz.x, h.x, fmaf(wz.y, h.y, fmaf(wz.z, h.z, fmaf(wz.w, h.w, acc[1][q]))));
                acc[2][q] = fmaf(wn.x, h.x, fmaf(wn.y, h.y, fmaf(wn.z, h.z, fmaf(wn.w, h.w, acc[2][q]))));
            }
        }

#pragma unroll
        for (int g = 0; g < 3; g++)
#pragma unroll
            for (int q0 = 0; q0 < 16; q0 += 4) {
                float4 v = make_float4(acc[g][q0], acc[g][q0 + 1], acc[g][q0 + 2], acc[g][q0 + 3]);
                *(float4*)(pp + g * 8 * PSTR + q0) = v;
            }
        __syncthreads();

        {
            int o = tid;
            int r = o >> 4, b = o & 15;
            float s = 0.f;
#pragma unroll
            for (int ks = 0; ks < 32; ks++) s += part[r * PSTR + (ks << 4) + b];
            ghs[o] = s + bh[r];
            if (tid < 128) {
                o = 256 + tid;
                r = o >> 4; b = o & 15;
                s = 0.f;
#pragma unroll
                for (int ks = 0; ks < 32; ks++) s += part[r * PSTR + (ks << 4) + b];
                ghs[o] = s + bh[r];
            }
        }
        __syncthreads();

        if (tid < 128) {
            int jj = tid & 7;
            int b  = tid >> 3;
            size_t mrow = (size_t)((b << 10) + t);
            const float* gxp = gx + mrow * 3072 + jbase + jj;
            float xr = gxp[0], xz = gxp[1024], xn = gxp[2048];
            float ghr = ghs[jj * 16 + b];
            float ghz = ghs[(8 + jj) * 16 + b];
            float ghn = ghs[(16 + jj) * 16 + b];
            float rg = 1.f / (1.f + expf(-(xr + ghr)));
            float zg = 1.f / (1.f + expf(-(xz + ghz)));
            float ng = tanhf(xn + rg * ghn);
            float hprev = hs[(b << 10) + jbase + jj];
            __stcg(hseq + mrow * 1024 + jbase + jj, (1.f - zg) * ng + zg * hprev);
        }

        gen++;
        __threadfence();
        __syncthreads();
        if (tid == 0) {
            unsigned arr = atomicAdd(&g_bar_in, 1u);
            if (arr == (unsigned)SCAN_G * gen - 1u) {
                atomicExch(&g_bar_gen, gen);
            } else {
                while (atomicAdd(&g_bar_gen, 0u) < gen) __nanosleep(32);
            }
            __threadfence();
        }
        __syncthreads();
    }
}

// ===========================================================================
// log_softmax over axis=1 (T)
// ===========================================================================
__global__ void __launch_bounds__(1024) lse_kernel(
    const float* __restrict__ logits, float* __restrict__ lse)
{
    __shared__ float sm_m[1024], sm_s[1024];
    const int b = blockIdx.x;
    const int tid = threadIdx.x;
    const int c = tid & 127, ts = tid >> 7;
    const float* p = logits + ((size_t)((b << 10) + (ts << 7))) * NCLS + c;
    float m = -1e30f, s = 0.f;
    for (int i = 0; i < 128; i++) {
        float x = p[(size_t)i * NCLS];
        if (x > m) { s = s * expf(m - x) + 1.f; m = x; }
        else       { s += expf(x - m); }
    }
    sm_m[tid] = m; sm_s[tid] = s;
    __syncthreads();
    if (tid < 128) {
        float M = sm_m[tid], S = sm_s[tid];
#pragma unroll
        for (int k = 1; k < 8; k++) {
            float m2 = sm_m[tid + k * 128], s2 = sm_s[tid + k * 128];
            if (m2 > M) { S = S * expf(M - m2) + s2; M = m2; }
            else        { S += s2 * expf(m2 - M); }
        }
        lse[b * NCLS + tid] = M + logf(S);
    }
}

__global__ void sub_kernel(float* __restrict__ out, const float* __restrict__ lse)
{
    int idx = blockIdx.x * blockDim.x + threadIdx.x;
    int b = idx >> 17;
    int c = idx & 127;
    out[idx] -= lse[(b << 7) + c];
}

// ===========================================================================
extern "C" void kernel_launch(void* const* d_in, const int* in_sizes, int n_in,
                              void* d_out, int out_size)
{
    (void)in_sizes; (void)n_in; (void)out_size;
    const int*   tok  = (const int*)d_in[0];
    const float* emb  = (const float*)d_in[1];
    const float* Wih0 = (const float*)d_in[2];
    const float* Whh0 = (const float*)d_in[3];
    const float* bih0 = (const float*)d_in[4];
    const float* bhh0 = (const float*)d_in[5];
    const float* Wih1 = (const float*)d_in[6];
    const float* Whh1 = (const float*)d_in[7];
    const float* bih1 = (const float*)d_in[8];
    const float* bhh1 = (const float*)d_in[9];
    const float* Wlin = (const float*)d_in[10];
    const float* blin = (const float*)d_in[11];
    float* out = (float*)d_out;

    float *gx, *hseq, *lseb;
    __nv_bfloat16 *a16, *b16;
    cudaGetSymbolAddress((void**)&gx,   g_gx);
    cudaGetSymbolAddress((void**)&hseq, g_hseq);
    cudaGetSymbolAddress((void**)&lseb, g_lse);
    cudaGetSymbolAddress((void**)&a16,  g_a16);
    cudaGetSymbolAddress((void**)&b16,  g_b16);

    cudaFuncSetAttribute(scan_kernel, cudaFuncAttributeMaxDynamicSharedMemorySize,
                         SCAN_SMEM_BYTES);
    cudaFuncSetAttribute(gemm_bf16, cudaFuncAttributeMaxDynamicSharedMemorySize,
                         GEMM_SMEM_BYTES);

    const size_t a_tot4 = ((size_t)MTOT * HD) / 4;
    const size_t w_tot4 = ((size_t)G3H * HD) / 4;
    const size_t l_tot4 = ((size_t)NCLS * HD) / 4;
    const int CB = 256;

    dim3 gG(MTOT / 128, G3H / 128);   // (128, 24)
    dim3 gL(MTOT / 128, 1);

    // ---- Layer 0 ----
    conv_bf16<<<(unsigned)((a_tot4 + CB - 1) / CB), CB>>>(emb, tok, a16, a_tot4);
    conv_bf16<<<(unsigned)((w_tot4 + CB - 1) / CB), CB>>>(Wih0, nullptr, b16, w_tot4);
    gemm_bf16<<<gG, 256, GEMM_SMEM_BYTES>>>(a16, b16, bih0, gx, G3H);
    bar_reset<<<1, 1>>>();
    scan_kernel<<<SCAN_G, 256, SCAN_SMEM_BYTES>>>(gx, Whh0, bhh0, hseq);

    // ---- Layer 1 ----
    conv_bf16<<<(unsigned)((a_tot4 + CB - 1) / CB), CB>>>(hseq, nullptr, a16, a_tot4);
    conv_bf16<<<(unsigned)((w_tot4 + CB - 1) / CB), CB>>>(Wih1, nullptr, b16, w_tot4);
    gemm_bf16<<<gG, 256, GEMM_SMEM_BYTES>>>(a16, b16, bih1, gx, G3H);
    bar_reset<<<1, 1>>>();
    scan_kernel<<<SCAN_G, 256, SCAN_SMEM_BYTES>>>(gx, Whh1, bhh1, hseq);

    // ---- Head ----
    conv_bf16<<<(unsigned)((a_tot4 + CB - 1) / CB), CB>>>(hseq, nullptr, a16, a_tot4);
    conv_bf16<<<(unsigned)((l_tot4 + CB - 1) / CB), CB>>>(Wlin, nullptr, b16, l_tot4);
    gemm_bf16<<<gL, 256, GEMM_SMEM_BYTES>>>(a16, b16, blin, out, NCLS);

    // ---- log_softmax over T ----
    lse_kernel<<<BATCH, 1024>>>(out, lseb);
    sub_kernel<<<(MTOT * NCLS) / 1024, 1024>>>(out, lseb);
}

// round 8
// speedup vs baseline: 5.2799x; 1.9129x over previous
#include <cuda_runtime.h>
#include <cuda_bf16.h>
#include <cstdint>
#include <math.h>

#define BATCH 16
#define TSEQ  1024
#define HD    1024
#define MTOT  (BATCH * TSEQ)   // 16384
#define G3H   (3 * HD)         // 3072
#define NCLS  128

__device__ float g_gx[(size_t)MTOT * G3H];           // 192 MB
__device__ __nv_bfloat16 g_h16[(size_t)MTOT * HD];   // 32 MB (h sequence, bf16)
__device__ __nv_bfloat16 g_a16[(size_t)MTOT * HD];   // 32 MB (gathered emb)
__device__ __nv_bfloat16 g_b16[(size_t)G3H * HD];    // 6 MB  (weights bf16)
__device__ float g_lse[BATCH * NCLS];
__device__ unsigned g_bar_in;
__device__ unsigned g_bar_gen;

// ===========================================================================
// fp32 -> bf16 convert (optionally gathering rows via tok); rows are K=1024
// ===========================================================================
__global__ void __launch_bounds__(256) conv_bf16(
    const float* __restrict__ in, const int* __restrict__ tok,
    __nv_bfloat16* __restrict__ out, size_t total4)
{
    size_t idx = (size_t)blockIdx.x * blockDim.x + threadIdx.x;
    if (idx >= total4) return;
    size_t e = idx << 2;
    size_t m = e >> 10;
    int    k = (int)(e & 1023);
    size_t srow = tok ? (size_t)tok[m] : m;
    float4 v = *(const float4*)(in + srow * 1024 + k);
    __nv_bfloat162 p0 = __floats2bfloat162_rn(v.x, v.y);
    __nv_bfloat162 p1 = __floats2bfloat162_rn(v.z, v.w);
    *(__nv_bfloat162*)(out + e)     = p0;
    *(__nv_bfloat162*)(out + e + 2) = p1;
}

// ===========================================================================
// Shared helpers
// ===========================================================================
__device__ __forceinline__ uint32_t smem_u32(const void* p) {
    uint32_t a;
    asm("{ .reg .u64 t; cvta.to.shared.u64 t, %1; cvt.u32.u64 %0, t; }"
        : "=r"(a) : "l"(p));
    return a;
}

__device__ __forceinline__ void ldsm_x4(uint32_t* r, uint32_t addr) {
    asm volatile("ldmatrix.sync.aligned.m8n8.x4.shared.b16 {%0,%1,%2,%3}, [%4];"
                 : "=r"(r[0]), "=r"(r[1]), "=r"(r[2]), "=r"(r[3]) : "r"(addr));
}

__device__ __forceinline__ void mma16(float* d, const uint32_t* a, uint32_t b0, uint32_t b1) {
    asm volatile(
        "mma.sync.aligned.m16n8k16.row.col.f32.bf16.bf16.f32 "
        "{%0,%1,%2,%3}, {%4,%5,%6,%7}, {%8,%9}, {%0,%1,%2,%3};"
        : "+f"(d[0]), "+f"(d[1]), "+f"(d[2]), "+f"(d[3])
        : "r"(a[0]), "r"(a[1]), "r"(a[2]), "r"(a[3]), "r"(b0), "r"(b1));
}

__device__ __forceinline__ uint32_t pk_bf16x2(float lo, float hi) {
    __nv_bfloat162 p = __floats2bfloat162_rn(lo, hi);
    return *reinterpret_cast<uint32_t*>(&p);
}

// ===========================================================================
// bf16 mma.sync GEMM: C[m,n] = sum_k A16[m,k]*B16[n,k] + bias[n]
// (unchanged from R7 — validated)
// ===========================================================================
#define RSTR_B 144
#define TILE_B (128 * RSTR_B)
#define GEMM_SMEM_BYTES (4 * TILE_B)

__global__ void __launch_bounds__(256) gemm_bf16(
    const __nv_bfloat16* __restrict__ A16,
    const __nv_bfloat16* __restrict__ B16,
    const float* __restrict__ bias,
    float* __restrict__ C, int N)
{
    extern __shared__ char smc[];
    const uint32_t sbase = smem_u32(smc);
    const int tid  = threadIdx.x;
    const int lane = tid & 31;
    const int warp = tid >> 5;
    const int bm = blockIdx.x * 128;
    const int bn = blockIdx.y * 128;
    const int wm = (warp & 1) * 64;
    const int wn = (warp >> 1) * 32;
    const int qr = lane >> 2;
    const int qc = lane & 3;

    const int r0 = tid >> 3;
    const int ch = tid & 7;
    const __nv_bfloat16* Ap = A16 + (size_t)(bm + r0) * 1024 + ch * 8;
    const __nv_bfloat16* Bp = B16 + (size_t)(bn + r0) * 1024 + ch * 8;
    const uint32_t s_off = (uint32_t)(r0 * RSTR_B + ch * 16);

    const uint32_t a_lm = (uint32_t)((wm + (lane & 15)) * RSTR_B + (lane >> 4) * 16);
    const uint32_t b_lm = (uint32_t)((wn + ((lane >> 4) & 1) * 8 + (lane & 7)) * RSTR_B
                                     + ((lane >> 3) & 1) * 16);

    float acc[4][4][4];
#pragma unroll
    for (int mf = 0; mf < 4; mf++)
#pragma unroll
        for (int nf = 0; nf < 4; nf++)
#pragma unroll
            for (int i = 0; i < 4; i++) acc[mf][nf][i] = 0.f;

    uint4 ra[4], rb[4];
#pragma unroll
    for (int l = 0; l < 4; l++) {
        ra[l] = *(const uint4*)(Ap + l * 32 * 1024);
        rb[l] = *(const uint4*)(Bp + l * 32 * 1024);
    }

    for (int it = 0; it < 16; it++) {
        const int buf = it & 1;
        const uint32_t abase = buf * (2 * TILE_B);
        const uint32_t bbase = abase + TILE_B;

#pragma unroll
        for (int l = 0; l < 4; l++) {
            *(uint4*)(smc + abase + s_off + l * 32 * RSTR_B) = ra[l];
            *(uint4*)(smc + bbase + s_off + l * 32 * RSTR_B) = rb[l];
        }
        __syncthreads();

        if (it + 1 < 16) {
            const size_t kofs = (size_t)(it + 1) * 64;
#pragma unroll
            for (int l = 0; l < 4; l++) {
                ra[l] = *(const uint4*)(Ap + l * 32 * 1024 + kofs);
                rb[l] = *(const uint4*)(Bp + l * 32 * 1024 + kofs);
            }
        }

        const uint32_t sA = sbase + abase + a_lm;
        const uint32_t sB = sbase + bbase + b_lm;
#pragma unroll
        for (int ks = 0; ks < 4; ks++) {
            uint32_t af[4][4], bb[2][4];
#pragma unroll
            for (int mf = 0; mf < 4; mf++)
                ldsm_x4(af[mf], sA + mf * 16 * RSTR_B + ks * 32);
#pragma unroll
            for (int np = 0; np < 2; np++)
                ldsm_x4(bb[np], sB + np * 16 * RSTR_B + ks * 32);
#pragma unroll
            for (int mf = 0; mf < 4; mf++) {
                mma16(acc[mf][0], af[mf], bb[0][0], bb[0][1]);
                mma16(acc[mf][1], af[mf], bb[0][2], bb[0][3]);
                mma16(acc[mf][2], af[mf], bb[1][0], bb[1][1]);
                mma16(acc[mf][3], af[mf], bb[1][2], bb[1][3]);
            }
        }
    }

#pragma unroll
    for (int nf = 0; nf < 4; nf++) {
        const int c = bn + wn + nf * 8 + 2 * qc;
        const float b0 = bias[c], b1 = bias[c + 1];
#pragma unroll
        for (int mf = 0; mf < 4; mf++) {
            const int rr = bm + wm + mf * 16 + qr;
            float2 v0 = make_float2(acc[mf][nf][0] + b0, acc[mf][nf][1] + b1);
            float2 v1 = make_float2(acc[mf][nf][2] + b0, acc[mf][nf][3] + b1);
            *(float2*)(C + (size_t)rr * N + c) = v0;
            *(float2*)(C + (size_t)(rr + 8) * N + c) = v1;
        }
    }
}

// ===========================================================================
// Tensor-core persistent GRU scan. 128 CTAs x 256 threads (8 warps).
// CTA owns 8 hidden j's (N=24 gate-outputs). Warp w owns K-slice [w*128,+128):
// W_hh fragments live in registers for all 1024 steps. h staged bf16 in smem
// (row stride 1032 -> conflict-free ldmatrix); h state chain kept fp32.
// ===========================================================================
#define SCAN_G 128
#define HSTR 1032   // bf16 elements per smem h row (2064 B)

__global__ void bar_reset() { g_bar_in = 0u; g_bar_gen = 0u; }

__global__ void __launch_bounds__(256, 1) scan_tc(
    const float* __restrict__ gx,     // [MTOT][3072] fp32
    const float* __restrict__ Whh,    // [3072][1024] fp32
    const float* __restrict__ bhh,    // [3072]
    __nv_bfloat16* __restrict__ h16)  // [MTOT][1024] bf16 (in: prev layer n/a; out: h)
{
    __shared__ __nv_bfloat16 hs[16 * HSTR];     // 33,024 B
    __shared__ float part[8 * 16 * 26];         // 13,312 B
    __shared__ float ghs[384];                  // [b][24]
    __shared__ float hp32[128];                 // [b][8] fp32 h state (own j's)
    __shared__ float bh[24];

    const int tid  = threadIdx.x;
    const int lane = tid & 31;
    const int warp = tid >> 5;
    const int jbase = blockIdx.x * 8;

    // --- Load W_hh fragments (fp32 -> bf16), resident for whole scan ---
    uint32_t wf[3][8][2];
    {
        const int jj = lane >> 2;
        const int kq = (lane & 3) * 2;
#pragma unroll
        for (int g = 0; g < 3; g++) {
            const float* wrow = Whh + (size_t)((g << 10) + jbase + jj) * 1024
                              + warp * 128 + kq;
#pragma unroll
            for (int kt = 0; kt < 8; kt++) {
                float2 lo = *(const float2*)(wrow + kt * 16);
                float2 hi = *(const float2*)(wrow + kt * 16 + 8);
                wf[g][kt][0] = pk_bf16x2(lo.x, lo.y);
                wf[g][kt][1] = pk_bf16x2(hi.x, hi.y);
            }
        }
    }
    if (tid < 24) bh[tid] = bhh[((tid >> 3) << 10) + jbase + (tid & 7)];
    if (tid < 128) hp32[tid] = 0.f;
    __syncthreads();

    const uint32_t hs_b = smem_u32(hs);
    const uint32_t a_base = hs_b + (uint32_t)((lane & 15) * (HSTR * 2)
                           + (lane >> 4) * 16 + warp * 256);

    unsigned gen = 0;
    for (int t = 0; t < TSEQ; t++) {
        // ---- Stage h_{t-1} (bf16) into smem ----
        if (t == 0) {
#pragma unroll
            for (int l = 0; l < 8; l++) {
                int u = tid + l * 256;
                int b = u >> 7, c = u & 127;
                *(uint4*)((char*)hs + b * (HSTR * 2) + c * 16) = make_uint4(0, 0, 0, 0);
            }
        } else {
#pragma unroll
            for (int l = 0; l < 8; l++) {
                int u = tid + l * 256;
                int b = u >> 7, c = u & 127;
                uint4 v = __ldcg((const uint4*)(h16 + ((size_t)((b << 10) + (t - 1))) * 1024 + c * 8));
                *(uint4*)((char*)hs + b * (HSTR * 2) + c * 16) = v;
            }
        }

        // Prefetch gx for gate threads (consumed after reduce)
        float xr = 0.f, xz = 0.f, xn = 0.f;
        if (tid < 128) {
            int jj = tid & 7, b = tid >> 3;
            const float* gxp = gx + ((size_t)((b << 10) + t)) * 3072 + jbase + jj;
            xr = gxp[0]; xz = gxp[1024]; xn = gxp[2048];
        }
        __syncthreads();

        // ---- MMA over this warp's K=128 slice ----
        float acc[3][4];
#pragma unroll
        for (int g = 0; g < 3; g++)
#pragma unroll
            for (int i = 0; i < 4; i++) acc[g][i] = 0.f;

#pragma unroll
        for (int kt = 0; kt < 8; kt++) {
            uint32_t a[4];
            ldsm_x4(a, a_base + kt * 32);
            mma16(acc[0], a, wf[0][kt][0], wf[0][kt][1]);
            mma16(acc[1], a, wf[1][kt][0], wf[1][kt][1]);
            mma16(acc[2], a, wf[2][kt][0], wf[2][kt][1]);
        }

        // ---- Store warp partials: part[warp][b:16][nc:24 (pad 26)] ----
        {
            float* pw = part + warp * (16 * 26);
            const int r = lane >> 2;
            const int c2 = (lane & 3) * 2;
#pragma unroll
            for (int g = 0; g < 3; g++) {
                *(float2*)(pw + r * 26 + g * 8 + c2)       = make_float2(acc[g][0], acc[g][1]);
                *(float2*)(pw + (r + 8) * 26 + g * 8 + c2) = make_float2(acc[g][2], acc[g][3]);
            }
        }
        __syncthreads();

        // ---- Reduce 8 warps -> ghs[b*24+nc] (+ b_hh) ----
        if (tid < 192) {
#pragma unroll
            for (int rep = 0; rep < 2; rep++) {
                int o = tid + rep * 192;
                int b = o / 24, nc = o - b * 24;
                float s = 0.f;
#pragma unroll
                for (int w = 0; w < 8; w++) s += part[w * 416 + b * 26 + nc];
                ghs[o] = s + bh[nc];
            }
        }
        __syncthreads();

        // ---- Gate math + fp32 state update + bf16 h write ----
        if (tid < 128) {
            int jj = tid & 7, b = tid >> 3;
            float ghr = ghs[b * 24 + jj];
            float ghz = ghs[b * 24 + 8 + jj];
            float ghn = ghs[b * 24 + 16 + jj];
            float rg = 1.f / (1.f + expf(-(xr + ghr)));
            float zg = 1.f / (1.f + expf(-(xz + ghz)));
            float ng = tanhf(xn + rg * ghn);
            float hprev = hp32[tid];
            float hnew = (1.f - zg) * ng + zg * hprev;
            hp32[tid] = hnew;
            h16[((size_t)((b << 10) + t)) * 1024 + jbase + jj] = __float2bfloat16(hnew);
        }

        // ---- Grid barrier ----
        gen++;
        __threadfence();
        __syncthreads();
        if (tid == 0) {
            unsigned arr = atomicAdd(&g_bar_in, 1u);
            if (arr == (unsigned)SCAN_G * gen - 1u) {
                atomicExch(&g_bar_gen, gen);
            } else {
                while (atomicAdd(&g_bar_gen, 0u) < gen) __nanosleep(32);
            }
            __threadfence();
        }
        __syncthreads();
    }
}

// ===========================================================================
// log_softmax over axis=1 (T)
// ===========================================================================
__global__ void __launch_bounds__(1024) lse_kernel(
    const float* __restrict__ logits, float* __restrict__ lse)
{
    __shared__ float sm_m[1024], sm_s[1024];
    const int b = blockIdx.x;
    const int tid = threadIdx.x;
    const int c = tid & 127, ts = tid >> 7;
    const float* p = logits + ((size_t)((b << 10) + (ts << 7))) * NCLS + c;
    float m = -1e30f, s = 0.f;
    for (int i = 0; i < 128; i++) {
        float x = p[(size_t)i * NCLS];
        if (x > m) { s = s * expf(m - x) + 1.f; m = x; }
        else       { s += expf(x - m); }
    }
    sm_m[tid] = m; sm_s[tid] = s;
    __syncthreads();
    if (tid < 128) {
        float M = sm_m[tid], S = sm_s[tid];
#pragma unroll
        for (int k = 1; k < 8; k++) {
            float m2 = sm_m[tid + k * 128], s2 = sm_s[tid + k * 128];
            if (m2 > M) { S = S * expf(M - m2) + s2; M = m2; }
            else        { S += s2 * expf(m2 - M); }
        }
        lse[b * NCLS + tid] = M + logf(S);
    }
}

__global__ void sub_kernel(float* __restrict__ out, const float* __restrict__ lse)
{
    int idx = blockIdx.x * blockDim.x + threadIdx.x;
    int b = idx >> 17;
    int c = idx & 127;
    out[idx] -= lse[(b << 7) + c];
}

// ===========================================================================
extern "C" void kernel_launch(void* const* d_in, const int* in_sizes, int n_in,
                              void* d_out, int out_size)
{
    (void)in_sizes; (void)n_in; (void)out_size;
    const int*   tok  = (const int*)d_in[0];
    const float* emb  = (const float*)d_in[1];
    const float* Wih0 = (const float*)d_in[2];
    const float* Whh0 = (const float*)d_in[3];
    const float* bih0 = (const float*)d_in[4];
    const float* bhh0 = (const float*)d_in[5];
    const float* Wih1 = (const float*)d_in[6];
    const float* Whh1 = (const float*)d_in[7];
    const float* bih1 = (const float*)d_in[8];
    const float* bhh1 = (const float*)d_in[9];
    const float* Wlin = (const float*)d_in[10];
    const float* blin = (const float*)d_in[11];
    float* out = (float*)d_out;

    float *gx, *lseb;
    __nv_bfloat16 *h16, *a16, *b16;
    cudaGetSymbolAddress((void**)&gx,   g_gx);
    cudaGetSymbolAddress((void**)&lseb, g_lse);
    cudaGetSymbolAddress((void**)&h16,  g_h16);
    cudaGetSymbolAddress((void**)&a16,  g_a16);
    cudaGetSymbolAddress((void**)&b16,  g_b16);

    cudaFuncSetAttribute(gemm_bf16, cudaFuncAttributeMaxDynamicSharedMemorySize,
                         GEMM_SMEM_BYTES);

    const size_t a_tot4 = ((size_t)MTOT * HD) / 4;
    const size_t w_tot4 = ((size_t)G3H * HD) / 4;
    const size_t l_tot4 = ((size_t)NCLS * HD) / 4;
    const int CB = 256;

    dim3 gG(MTOT / 128, G3H / 128);   // (128, 24)
    dim3 gL(MTOT / 128, 1);

    // ---- Layer 0 ----
    conv_bf16<<<(unsigned)((a_tot4 + CB - 1) / CB), CB>>>(emb, tok, a16, a_tot4);
    conv_bf16<<<(unsigned)((w_tot4 + CB - 1) / CB), CB>>>(Wih0, nullptr, b16, w_tot4);
    gemm_bf16<<<gG, 256, GEMM_SMEM_BYTES>>>(a16, b16, bih0, gx, G3H);
    bar_reset<<<1, 1>>>();
    scan_tc<<<SCAN_G, 256>>>(gx, Whh0, bhh0, h16);

    // ---- Layer 1 (GEMM reads bf16 h directly) ----
    conv_bf16<<<(unsigned)((w_tot4 + CB - 1) / CB), CB>>>(Wih1, nullptr, b16, w_tot4);
    gemm_bf16<<<gG, 256, GEMM_SMEM_BYTES>>>(h16, b16, bih1, gx, G3H);
    bar_reset<<<1, 1>>>();
    scan_tc<<<SCAN_G, 256>>>(gx, Whh1, bhh1, h16);

    // ---- Head ----
    conv_bf16<<<(unsigned)((l_tot4 + CB - 1) / CB), CB>>>(Wlin, nullptr, b16, l_tot4);
    gemm_bf16<<<gL, 256, GEMM_SMEM_BYTES>>>(h16, b16, blin, out, NCLS);

    // ---- log_softmax over T ----
    lse_kernel<<<BATCH, 1024>>>(out, lseb);
    sub_kernel<<<(MTOT * NCLS) / 1024, 1024>>>(out, lseb);
}

// round 9
// speedup vs baseline: 5.3891x; 1.0207x over previous
#include <cuda_runtime.h>
#include <cuda_bf16.h>
#include <cstdint>
#include <math.h>

#define BATCH 16
#define TSEQ  1024
#define HD    1024
#define MTOT  (BATCH * TSEQ)   // 16384
#define G3H   (3 * HD)         // 3072
#define NCLS  128

__device__ float g_gx[(size_t)MTOT * G3H];           // 192 MB
__device__ __nv_bfloat16 g_h16[(size_t)MTOT * HD];   // 32 MB (h sequence, bf16)
__device__ __nv_bfloat16 g_a16[(size_t)MTOT * HD];   // 32 MB (gathered emb)
__device__ __nv_bfloat16 g_b16[(size_t)G3H * HD];    // 6 MB  (weights bf16)
__device__ float g_lse[BATCH * NCLS];
__device__ unsigned g_bar_in;

// ===========================================================================
// fp32 -> bf16 convert (optionally gathering rows via tok); rows are K=1024
// ===========================================================================
__global__ void __launch_bounds__(256) conv_bf16(
    const float* __restrict__ in, const int* __restrict__ tok,
    __nv_bfloat16* __restrict__ out, size_t total4)
{
    size_t idx = (size_t)blockIdx.x * blockDim.x + threadIdx.x;
    if (idx >= total4) return;
    size_t e = idx << 2;
    size_t m = e >> 10;
    int    k = (int)(e & 1023);
    size_t srow = tok ? (size_t)tok[m] : m;
    float4 v = *(const float4*)(in + srow * 1024 + k);
    __nv_bfloat162 p0 = __floats2bfloat162_rn(v.x, v.y);
    __nv_bfloat162 p1 = __floats2bfloat162_rn(v.z, v.w);
    *(__nv_bfloat162*)(out + e)     = p0;
    *(__nv_bfloat162*)(out + e + 2) = p1;
}

// ===========================================================================
// Shared helpers
// ===========================================================================
__device__ __forceinline__ uint32_t smem_u32(const void* p) {
    uint32_t a;
    asm("{ .reg .u64 t; cvta.to.shared.u64 t, %1; cvt.u32.u64 %0, t; }"
        : "=r"(a) : "l"(p));
    return a;
}

__device__ __forceinline__ void ldsm_x4(uint32_t* r, uint32_t addr) {
    asm volatile("ldmatrix.sync.aligned.m8n8.x4.shared.b16 {%0,%1,%2,%3}, [%4];"
                 : "=r"(r[0]), "=r"(r[1]), "=r"(r[2]), "=r"(r[3]) : "r"(addr));
}

__device__ __forceinline__ void mma16(float* d, const uint32_t* a, uint32_t b0, uint32_t b1) {
    asm volatile(
        "mma.sync.aligned.m16n8k16.row.col.f32.bf16.bf16.f32 "
        "{%0,%1,%2,%3}, {%4,%5,%6,%7}, {%8,%9}, {%0,%1,%2,%3};"
        : "+f"(d[0]), "+f"(d[1]), "+f"(d[2]), "+f"(d[3])
        : "r"(a[0]), "r"(a[1]), "r"(a[2]), "r"(a[3]), "r"(b0), "r"(b1));
}

__device__ __forceinline__ uint32_t pk_bf16x2(float lo, float hi) {
    __nv_bfloat162 p = __floats2bfloat162_rn(lo, hi);
    return *reinterpret_cast<uint32_t*>(&p);
}

// ===========================================================================
// bf16 mma.sync GEMM (unchanged from R7/R8 — validated)
// ===========================================================================
#define RSTR_B 144
#define TILE_B (128 * RSTR_B)
#define GEMM_SMEM_BYTES (4 * TILE_B)

__global__ void __launch_bounds__(256) gemm_bf16(
    const __nv_bfloat16* __restrict__ A16,
    const __nv_bfloat16* __restrict__ B16,
    const float* __restrict__ bias,
    float* __restrict__ C, int N)
{
    extern __shared__ char smc[];
    const uint32_t sbase = smem_u32(smc);
    const int tid  = threadIdx.x;
    const int lane = tid & 31;
    const int warp = tid >> 5;
    const int bm = blockIdx.x * 128;
    const int bn = blockIdx.y * 128;
    const int wm = (warp & 1) * 64;
    const int wn = (warp >> 1) * 32;
    const int qr = lane >> 2;
    const int qc = lane & 3;

    const int r0 = tid >> 3;
    const int ch = tid & 7;
    const __nv_bfloat16* Ap = A16 + (size_t)(bm + r0) * 1024 + ch * 8;
    const __nv_bfloat16* Bp = B16 + (size_t)(bn + r0) * 1024 + ch * 8;
    const uint32_t s_off = (uint32_t)(r0 * RSTR_B + ch * 16);

    const uint32_t a_lm = (uint32_t)((wm + (lane & 15)) * RSTR_B + (lane >> 4) * 16);
    const uint32_t b_lm = (uint32_t)((wn + ((lane >> 4) & 1) * 8 + (lane & 7)) * RSTR_B
                                     + ((lane >> 3) & 1) * 16);

    float acc[4][4][4];
#pragma unroll
    for (int mf = 0; mf < 4; mf++)
#pragma unroll
        for (int nf = 0; nf < 4; nf++)
#pragma unroll
            for (int i = 0; i < 4; i++) acc[mf][nf][i] = 0.f;

    uint4 ra[4], rb[4];
#pragma unroll
    for (int l = 0; l < 4; l++) {
        ra[l] = *(const uint4*)(Ap + l * 32 * 1024);
        rb[l] = *(const uint4*)(Bp + l * 32 * 1024);
    }

    for (int it = 0; it < 16; it++) {
        const int buf = it & 1;
        const uint32_t abase = buf * (2 * TILE_B);
        const uint32_t bbase = abase + TILE_B;

#pragma unroll
        for (int l = 0; l < 4; l++) {
            *(uint4*)(smc + abase + s_off + l * 32 * RSTR_B) = ra[l];
            *(uint4*)(smc + bbase + s_off + l * 32 * RSTR_B) = rb[l];
        }
        __syncthreads();

        if (it + 1 < 16) {
            const size_t kofs = (size_t)(it + 1) * 64;
#pragma unroll
            for (int l = 0; l < 4; l++) {
                ra[l] = *(const uint4*)(Ap + l * 32 * 1024 + kofs);
                rb[l] = *(const uint4*)(Bp + l * 32 * 1024 + kofs);
            }
        }

        const uint32_t sA = sbase + abase + a_lm;
        const uint32_t sB = sbase + bbase + b_lm;
#pragma unroll
        for (int ks = 0; ks < 4; ks++) {
            uint32_t af[4][4], bb[2][4];
#pragma unroll
            for (int mf = 0; mf < 4; mf++)
                ldsm_x4(af[mf], sA + mf * 16 * RSTR_B + ks * 32);
#pragma unroll
            for (int np = 0; np < 2; np++)
                ldsm_x4(bb[np], sB + np * 16 * RSTR_B + ks * 32);
#pragma unroll
            for (int mf = 0; mf < 4; mf++) {
                mma16(acc[mf][0], af[mf], bb[0][0], bb[0][1]);
                mma16(acc[mf][1], af[mf], bb[0][2], bb[0][3]);
                mma16(acc[mf][2], af[mf], bb[1][0], bb[1][1]);
                mma16(acc[mf][3], af[mf], bb[1][2], bb[1][3]);
            }
        }
    }

#pragma unroll
    for (int nf = 0; nf < 4; nf++) {
        const int c = bn + wn + nf * 8 + 2 * qc;
        const float b0 = bias[c], b1 = bias[c + 1];
#pragma unroll
        for (int mf = 0; mf < 4; mf++) {
            const int rr = bm + wm + mf * 16 + qr;
            float2 v0 = make_float2(acc[mf][nf][0] + b0, acc[mf][nf][1] + b1);
            float2 v1 = make_float2(acc[mf][nf][2] + b0, acc[mf][nf][3] + b1);
            *(float2*)(C + (size_t)rr * N + c) = v0;
            *(float2*)(C + (size_t)(rr + 8) * N + c) = v1;
        }
    }
}

// ===========================================================================
// Tensor-core persistent GRU scan, latency-optimized.
// 128 CTAs x 256 threads (8 warps). Warp w owns K-slice [w*128,+128): its
// W fragments are register-resident and its h slice is private smem (stage
// with only __syncwarp). Grid barrier: red.release arrival + ld.acquire
// poll by tid0, smem-flag fanout to other warps. Gate threads fuse the
// cross-warp reduction. 2 syncthreads per step.
// ===========================================================================
#define SCAN_G 128
#define HSTR 1032   // bf16 elements per smem h row (2064 B)

__global__ void bar_reset() { g_bar_in = 0u; }

__global__ void __launch_bounds__(256, 1) scan_tc(
    const float* __restrict__ gx,     // [MTOT][3072] fp32
    const float* __restrict__ Whh,    // [3072][1024] fp32
    const float* __restrict__ bhh,    // [3072]
    __nv_bfloat16* __restrict__ h16)  // [MTOT][1024] bf16
{
    __shared__ __nv_bfloat16 hs[16 * HSTR];     // 33,024 B
    __shared__ float part[8 * 16 * 26];         // 13,312 B
    __shared__ float hp32[128];
    __shared__ float bh[24];
    __shared__ volatile unsigned sflag;

    const int tid  = threadIdx.x;
    const int lane = tid & 31;
    const int warp = tid >> 5;
    const int jbase = blockIdx.x * 8;

    unsigned* bar_ptr = &g_bar_in;

    // --- W_hh fragments (fp32 -> bf16), register-resident for whole scan ---
    uint32_t wf[3][8][2];
    {
        const int jj = lane >> 2;
        const int kq = (lane & 3) * 2;
#pragma unroll
        for (int g = 0; g < 3; g++) {
            const float* wrow = Whh + (size_t)((g << 10) + jbase + jj) * 1024
                              + warp * 128 + kq;
#pragma unroll
            for (int kt = 0; kt < 8; kt++) {
                float2 lo = *(const float2*)(wrow + kt * 16);
                float2 hi = *(const float2*)(wrow + kt * 16 + 8);
                wf[g][kt][0] = pk_bf16x2(lo.x, lo.y);
                wf[g][kt][1] = pk_bf16x2(hi.x, hi.y);
            }
        }
    }
    if (tid < 24) bh[tid] = bhh[((tid >> 3) << 10) + jbase + (tid & 7)];
    if (tid < 128) hp32[tid] = 0.f;
    if (tid == 0) sflag = 0u;
    __syncthreads();

    const uint32_t hs_b = smem_u32(hs);
    const uint32_t a_base = hs_b + (uint32_t)((lane & 15) * (HSTR * 2)
                           + (lane >> 4) * 16 + warp * 256);
    // Staging role: lane handles 8 chunks of 16B within warp's 128-col slice
    const int st_b0 = lane >> 4;            // via u = lane + l*32: b = u>>4
    const int st_c  = lane & 15;

    for (int t = 0; t < TSEQ; t++) {
        // ---- Prefetch gx (independent of the barrier) ----
        float xr = 0.f, xz = 0.f, xn = 0.f;
        if (tid < 128) {
            int jj = tid & 7, b = tid >> 3;
            const float* gxp = gx + ((size_t)((b << 10) + t)) * 3072 + jbase + jj;
            xr = gxp[0]; xz = gxp[1024]; xn = gxp[2048];
        }

        // ---- Wait for step t-1 (all CTAs) ----
        if (t > 0) {
            if (tid == 0) {
                unsigned v;
                do {
                    asm volatile("ld.acquire.gpu.global.u32 %0, [%1];"
                                 : "=r"(v) : "l"(bar_ptr) : "memory");
                } while (v < (unsigned)(SCAN_G * t));
                sflag = (unsigned)t;
            } else if (lane == 0) {
                while (sflag < (unsigned)t) { }
            }
            __syncwarp();
        }

        // ---- Stage own K-slice of h_{t-1} (warp-private; bf16) ----
        if (t == 0) {
#pragma unroll
            for (int l = 0; l < 8; l++) {
                int b = st_b0 + l * 2;
                *(uint4*)((char*)hs + b * (HSTR * 2) + warp * 256 + st_c * 16) =
                    make_uint4(0, 0, 0, 0);
            }
        } else {
#pragma unroll
            for (int l = 0; l < 8; l++) {
                int b = st_b0 + l * 2;
                uint4 v = __ldcg((const uint4*)(h16 + ((size_t)((b << 10) + (t - 1))) * 1024
                                                + warp * 128 + st_c * 8));
                *(uint4*)((char*)hs + b * (HSTR * 2) + warp * 256 + st_c * 16) = v;
            }
        }
        __syncwarp();

        // ---- MMA over this warp's K=128 slice ----
        float acc[3][4];
#pragma unroll
        for (int g = 0; g < 3; g++)
#pragma unroll
            for (int i = 0; i < 4; i++) acc[g][i] = 0.f;

#pragma unroll
        for (int kt = 0; kt < 8; kt++) {
            uint32_t a[4];
            ldsm_x4(a, a_base + kt * 32);
            mma16(acc[0], a, wf[0][kt][0], wf[0][kt][1]);
            mma16(acc[1], a, wf[1][kt][0], wf[1][kt][1]);
            mma16(acc[2], a, wf[2][kt][0], wf[2][kt][1]);
        }

        // ---- Store warp partials: part[warp][b:16][nc:24 (pad 26)] ----
        {
            float* pw = part + warp * (16 * 26);
            const int r = lane >> 2;
            const int c2 = (lane & 3) * 2;
#pragma unroll
            for (int g = 0; g < 3; g++) {
                *(float2*)(pw + r * 26 + g * 8 + c2)       = make_float2(acc[g][0], acc[g][1]);
                *(float2*)(pw + (r + 8) * 26 + g * 8 + c2) = make_float2(acc[g][2], acc[g][3]);
            }
        }
        __syncthreads();

        // ---- Gates: fused 8-warp reduce + nonlinearity + h write ----
        if (tid < 128) {
            int jj = tid & 7, b = tid >> 3;
            float sr = bh[jj], sz = bh[8 + jj], sn = bh[16 + jj];
#pragma unroll
            for (int w = 0; w < 8; w++) {
                const float* pw = part + w * 416 + b * 26;
                sr += pw[jj];
                sz += pw[8 + jj];
                sn += pw[16 + jj];
            }
            float rg = 1.f / (1.f + expf(-(xr + sr)));
            float zg = 1.f / (1.f + expf(-(xz + sz)));
            float ng = tanhf(xn + rg * sn);
            float hprev = hp32[tid];
            float hnew = (1.f - zg) * ng + zg * hprev;
            hp32[tid] = hnew;
            __stcg((__nv_bfloat16*)(h16 + ((size_t)((b << 10) + t)) * 1024 + jbase + jj),
                   __float2bfloat16(hnew));
        }

        // ---- Publish + arrive ----
        __threadfence();
        __syncthreads();
        if (tid == 0) {
            asm volatile("red.release.gpu.global.add.u32 [%0], %1;"
                         :: "l"(bar_ptr), "r"(1u) : "memory");
        }
    }
}

// ===========================================================================
// log_softmax over axis=1 (T)
// ===========================================================================
__global__ void __launch_bounds__(1024) lse_kernel(
    const float* __restrict__ logits, float* __restrict__ lse)
{
    __shared__ float sm_m[1024], sm_s[1024];
    const int b = blockIdx.x;
    const int tid = threadIdx.x;
    const int c = tid & 127, ts = tid >> 7;
    const float* p = logits + ((size_t)((b << 10) + (ts << 7))) * NCLS + c;
    float m = -1e30f, s = 0.f;
    for (int i = 0; i < 128; i++) {
        float x = p[(size_t)i * NCLS];
        if (x > m) { s = s * expf(m - x) + 1.f; m = x; }
        else       { s += expf(x - m); }
    }
    sm_m[tid] = m; sm_s[tid] = s;
    __syncthreads();
    if (tid < 128) {
        float M = sm_m[tid], S = sm_s[tid];
#pragma unroll
        for (int k = 1; k < 8; k++) {
            float m2 = sm_m[tid + k * 128], s2 = sm_s[tid + k * 128];
            if (m2 > M) { S = S * expf(M - m2) + s2; M = m2; }
            else        { S += s2 * expf(m2 - M); }
        }
        lse[b * NCLS + tid] = M + logf(S);
    }
}

__global__ void sub_kernel(float* __restrict__ out, const float* __restrict__ lse)
{
    int idx = blockIdx.x * blockDim.x + threadIdx.x;
    int b = idx >> 17;
    int c = idx & 127;
    out[idx] -= lse[(b << 7) + c];
}

// ===========================================================================
extern "C" void kernel_launch(void* const* d_in, const int* in_sizes, int n_in,
                              void* d_out, int out_size)
{
    (void)in_sizes; (void)n_in; (void)out_size;
    const int*   tok  = (const int*)d_in[0];
    const float* emb  = (const float*)d_in[1];
    const float* Wih0 = (const float*)d_in[2];
    const float* Whh0 = (const float*)d_in[3];
    const float* bih0 = (const float*)d_in[4];
    const float* bhh0 = (const float*)d_in[5];
    const float* Wih1 = (const float*)d_in[6];
    const float* Whh1 = (const float*)d_in[7];
    const float* bih1 = (const float*)d_in[8];
    const float* bhh1 = (const float*)d_in[9];
    const float* Wlin = (const float*)d_in[10];
    const float* blin = (const float*)d_in[11];
    float* out = (float*)d_out;

    float *gx, *lseb;
    __nv_bfloat16 *h16, *a16, *b16;
    cudaGetSymbolAddress((void**)&gx,   g_gx);
    cudaGetSymbolAddress((void**)&lseb, g_lse);
    cudaGetSymbolAddress((void**)&h16,  g_h16);
    cudaGetSymbolAddress((void**)&a16,  g_a16);
    cudaGetSymbolAddress((void**)&b16,  g_b16);

    cudaFuncSetAttribute(gemm_bf16, cudaFuncAttributeMaxDynamicSharedMemorySize,
                         GEMM_SMEM_BYTES);

    const size_t a_tot4 = ((size_t)MTOT * HD) / 4;
    const size_t w_tot4 = ((size_t)G3H * HD) / 4;
    const size_t l_tot4 = ((size_t)NCLS * HD) / 4;
    const int CB = 256;

    dim3 gG(MTOT / 128, G3H / 128);   // (128, 24)
    dim3 gL(MTOT / 128, 1);

    // ---- Layer 0 ----
    conv_bf16<<<(unsigned)((a_tot4 + CB - 1) / CB), CB>>>(emb, tok, a16, a_tot4);
    conv_bf16<<<(unsigned)((w_tot4 + CB - 1) / CB), CB>>>(Wih0, nullptr, b16, w_tot4);
    gemm_bf16<<<gG, 256, GEMM_SMEM_BYTES>>>(a16, b16, bih0, gx, G3H);
    bar_reset<<<1, 1>>>();
    scan_tc<<<SCAN_G, 256>>>(gx, Whh0, bhh0, h16);

    // ---- Layer 1 (GEMM reads bf16 h directly) ----
    conv_bf16<<<(unsigned)((w_tot4 + CB - 1) / CB), CB>>>(Wih1, nullptr, b16, w_tot4);
    gemm_bf16<<<gG, 256, GEMM_SMEM_BYTES>>>(h16, b16, bih1, gx, G3H);
    bar_reset<<<1, 1>>>();
    scan_tc<<<SCAN_G, 256>>>(gx, Whh1, bhh1, h16);

    // ---- Head ----
    conv_bf16<<<(unsigned)((l_tot4 + CB - 1) / CB), CB>>>(Wlin, nullptr, b16, l_tot4);
    gemm_bf16<<<gL, 256, GEMM_SMEM_BYTES>>>(h16, b16, blin, out, NCLS);

    // ---- log_softmax over T ----
    lse_kernel<<<BATCH, 1024>>>(out, lseb);
    sub_kernel<<<(MTOT * NCLS) / 1024, 1024>>>(out, lseb);
}

// round 10
// speedup vs baseline: 9.2418x; 1.7149x over previous
#include <cuda_runtime.h>
#include <cuda_bf16.h>
#include <cstdint>
#include <math.h>

#define BATCH 16
#define TSEQ  1024
#define HD    1024
#define MTOT  (BATCH * TSEQ)   // 16384
#define G3H   (3 * HD)         // 3072
#define NCLS  128

__device__ float g_gx[(size_t)MTOT * G3H];           // layer-0 input gates (fp32)
__device__ __nv_bfloat16 g_h1[(size_t)MTOT * HD];    // layer-0 hidden seq
__device__ __nv_bfloat16 g_h2[(size_t)MTOT * HD];    // layer-1 hidden seq
__device__ __nv_bfloat16 g_a16[(size_t)MTOT * HD];   // gathered emb (bf16)
__device__ __nv_bfloat16 g_b16[(size_t)G3H * HD];    // weights (bf16)
__device__ float g_lse[BATCH * NCLS];
__device__ unsigned g_cnt[2];

// ===========================================================================
// fp32 -> bf16 convert (optionally gathering rows via tok); rows are K=1024
// ===========================================================================
__global__ void __launch_bounds__(256) conv_bf16(
    const float* __restrict__ in, const int* __restrict__ tok,
    __nv_bfloat16* __restrict__ out, size_t total4)
{
    size_t idx = (size_t)blockIdx.x * blockDim.x + threadIdx.x;
    if (idx >= total4) return;
    size_t e = idx << 2;
    size_t m = e >> 10;
    int    k = (int)(e & 1023);
    size_t srow = tok ? (size_t)tok[m] : m;
    float4 v = *(const float4*)(in + srow * 1024 + k);
    __nv_bfloat162 p0 = __floats2bfloat162_rn(v.x, v.y);
    __nv_bfloat162 p1 = __floats2bfloat162_rn(v.z, v.w);
    *(__nv_bfloat162*)(out + e)     = p0;
    *(__nv_bfloat162*)(out + e + 2) = p1;
}

// ===========================================================================
// Shared helpers
// ===========================================================================
__device__ __forceinline__ uint32_t smem_u32(const void* p) {
    uint32_t a;
    asm("{ .reg .u64 t; cvta.to.shared.u64 t, %1; cvt.u32.u64 %0, t; }"
        : "=r"(a) : "l"(p));
    return a;
}

__device__ __forceinline__ void ldsm_x4(uint32_t* r, uint32_t addr) {
    asm volatile("ldmatrix.sync.aligned.m8n8.x4.shared.b16 {%0,%1,%2,%3}, [%4];"
                 : "=r"(r[0]), "=r"(r[1]), "=r"(r[2]), "=r"(r[3]) : "r"(addr));
}

__device__ __forceinline__ void mma16(float* d, const uint32_t* a, uint32_t b0, uint32_t b1) {
    asm volatile(
        "mma.sync.aligned.m16n8k16.row.col.f32.bf16.bf16.f32 "
        "{%0,%1,%2,%3}, {%4,%5,%6,%7}, {%8,%9}, {%0,%1,%2,%3};"
        : "+f"(d[0]), "+f"(d[1]), "+f"(d[2]), "+f"(d[3])
        : "r"(a[0]), "r"(a[1]), "r"(a[2]), "r"(a[3]), "r"(b0), "r"(b1));
}

__device__ __forceinline__ uint32_t pk_bf16x2(float lo, float hi) {
    __nv_bfloat162 p = __floats2bfloat162_rn(lo, hi);
    return *reinterpret_cast<uint32_t*>(&p);
}

__device__ __forceinline__ unsigned ld_acq(const unsigned* p) {
    unsigned v;
    asm volatile("ld.acquire.gpu.global.u32 %0, [%1];" : "=r"(v) : "l"(p) : "memory");
    return v;
}

__device__ __forceinline__ void red_rel(unsigned* p) {
    asm volatile("red.release.gpu.global.add.u32 [%0], %1;" :: "l"(p), "r"(1u) : "memory");
}

// ===========================================================================
// bf16 mma.sync GEMM (validated R7)
// ===========================================================================
#define RSTR_B 144
#define TILE_B (128 * RSTR_B)
#define GEMM_SMEM_BYTES (4 * TILE_B)

__global__ void __launch_bounds__(256) gemm_bf16(
    const __nv_bfloat16* __restrict__ A16,
    const __nv_bfloat16* __restrict__ B16,
    const float* __restrict__ bias,
    float* __restrict__ C, int N)
{
    extern __shared__ char smc[];
    const uint32_t sbase = smem_u32(smc);
    const int tid  = threadIdx.x;
    const int lane = tid & 31;
    const int warp = tid >> 5;
    const int bm = blockIdx.x * 128;
    const int bn = blockIdx.y * 128;
    const int wm = (warp & 1) * 64;
    const int wn = (warp >> 1) * 32;
    const int qr = lane >> 2;
    const int qc = lane & 3;

    const int r0 = tid >> 3;
    const int ch = tid & 7;
    const __nv_bfloat16* Ap = A16 + (size_t)(bm + r0) * 1024 + ch * 8;
    const __nv_bfloat16* Bp = B16 + (size_t)(bn + r0) * 1024 + ch * 8;
    const uint32_t s_off = (uint32_t)(r0 * RSTR_B + ch * 16);

    const uint32_t a_lm = (uint32_t)((wm + (lane & 15)) * RSTR_B + (lane >> 4) * 16);
    const uint32_t b_lm = (uint32_t)((wn + ((lane >> 4) & 1) * 8 + (lane & 7)) * RSTR_B
                                     + ((lane >> 3) & 1) * 16);

    float acc[4][4][4];
#pragma unroll
    for (int mf = 0; mf < 4; mf++)
#pragma unroll
        for (int nf = 0; nf < 4; nf++)
#pragma unroll
            for (int i = 0; i < 4; i++) acc[mf][nf][i] = 0.f;

    uint4 ra[4], rb[4];
#pragma unroll
    for (int l = 0; l < 4; l++) {
        ra[l] = *(const uint4*)(Ap + l * 32 * 1024);
        rb[l] = *(const uint4*)(Bp + l * 32 * 1024);
    }

    for (int it = 0; it < 16; it++) {
        const int buf = it & 1;
        const uint32_t abase = buf * (2 * TILE_B);
        const uint32_t bbase = abase + TILE_B;

#pragma unroll
        for (int l = 0; l < 4; l++) {
            *(uint4*)(smc + abase + s_off + l * 32 * RSTR_B) = ra[l];
            *(uint4*)(smc + bbase + s_off + l * 32 * RSTR_B) = rb[l];
        }
        __syncthreads();

        if (it + 1 < 16) {
            const size_t kofs = (size_t)(it + 1) * 64;
#pragma unroll
            for (int l = 0; l < 4; l++) {
                ra[l] = *(const uint4*)(Ap + l * 32 * 1024 + kofs);
                rb[l] = *(const uint4*)(Bp + l * 32 * 1024 + kofs);
            }
        }

        const uint32_t sA = sbase + abase + a_lm;
        const uint32_t sB = sbase + bbase + b_lm;
#pragma unroll
        for (int ks = 0; ks < 4; ks++) {
            uint32_t af[4][4], bb[2][4];
#pragma unroll
            for (int mf = 0; mf < 4; mf++)
                ldsm_x4(af[mf], sA + mf * 16 * RSTR_B + ks * 32);
#pragma unroll
            for (int np = 0; np < 2; np++)
                ldsm_x4(bb[np], sB + np * 16 * RSTR_B + ks * 32);
#pragma unroll
            for (int mf = 0; mf < 4; mf++) {
                mma16(acc[mf][0], af[mf], bb[0][0], bb[0][1]);
                mma16(acc[mf][1], af[mf], bb[0][2], bb[0][3]);
                mma16(acc[mf][2], af[mf], bb[1][0], bb[1][1]);
                mma16(acc[mf][3], af[mf], bb[1][2], bb[1][3]);
            }
        }
    }

#pragma unroll
    for (int nf = 0; nf < 4; nf++) {
        const int c = bn + wn + nf * 8 + 2 * qc;
        const float b0 = bias[c], b1 = bias[c + 1];
#pragma unroll
        for (int mf = 0; mf < 4; mf++) {
            const int rr = bm + wm + mf * 16 + qr;
            float2 v0 = make_float2(acc[mf][nf][0] + b0, acc[mf][nf][1] + b1);
            float2 v1 = make_float2(acc[mf][nf][2] + b0, acc[mf][nf][3] + b1);
            *(float2*)(C + (size_t)rr * N + c) = v0;
            *(float2*)(C + (size_t)(rr + 8) * N + c) = v1;
        }
    }
}

// ===========================================================================
// Fused two-layer pipelined GRU scan.
// Grid = 128 CTAs x 256 threads. CTAs 0..63: layer-0 (16 j's each).
// CTAs 64..127: layer-1 (16 j's each), lagging layer-0 by one step; its
// input-gate product (h1_t @ W_ih1^T) is a second mma pass with W_ih1 in smem.
// Counters: cnt0 = layer-0 steps, cnt1 = layer-1 steps (64 arrivals each).
// ===========================================================================
#define L0_CTAS 64
#define HROW 2064                 // smem h row stride bytes (1032 bf16)
#define PSTRIDE 66                // part row stride floats
// dyn smem layout (bytes)
#define SM_HS    0                // 16 * 2064 = 33024
#define SM_WIH   33024            // 48 * 2064 = 99072 (layer-1 only)
#define SM_PART  132096           // 8 * 16 * 66 * 4 = 33792
#define SM_BI    165888           // 48 * 4
#define SM_BH    166080           // 48 * 4
#define SM_HP    166272           // 256 * 4
#define SM_TOTAL 167296

__global__ void bar_reset() { g_cnt[0] = 0u; g_cnt[1] = 0u; }

__global__ void __launch_bounds__(256, 1) scan_fused(
    const float* __restrict__ gx0,
    const float* __restrict__ Whh0, const float* __restrict__ bhh0,
    const float* __restrict__ Wih1, const float* __restrict__ bih1,
    const float* __restrict__ Whh1, const float* __restrict__ bhh1,
    __nv_bfloat16* __restrict__ h1, __nv_bfloat16* __restrict__ h2)
{
    extern __shared__ char dsm[];
    __shared__ volatile unsigned sflagA;
    __shared__ volatile unsigned sflagB;

    char*  hs   = dsm + SM_HS;
    char*  wih  = dsm + SM_WIH;
    float* part = (float*)(dsm + SM_PART);
    float* bi   = (float*)(dsm + SM_BI);
    float* bh   = (float*)(dsm + SM_BH);
    float* hp32 = (float*)(dsm + SM_HP);

    const int tid  = threadIdx.x;
    const int lane = tid & 31;
    const int warp = tid >> 5;
    const bool is_l1 = blockIdx.x >= L0_CTAS;
    const int jbase = (is_l1 ? (int)blockIdx.x - L0_CTAS : (int)blockIdx.x) * 16;

    unsigned* cnt0 = &g_cnt[0];
    unsigned* cnt1 = &g_cnt[1];

    // ---- One-time setup ----
    if (is_l1) {
        // W_ih1 rows for this CTA's 48 gate-outputs -> smem bf16
        for (int f = tid; f < 48 * 256; f += 256) {
            int n = f >> 8, c4 = f & 255;
            int g = n >> 4, jj = n & 15;
            float4 v = *(const float4*)(Wih1 + (size_t)(g * 1024 + jbase + jj) * 1024 + c4 * 4);
            uint2 pk;
            pk.x = pk_bf16x2(v.x, v.y);
            pk.y = pk_bf16x2(v.z, v.w);
            *(uint2*)(wih + n * HROW + c4 * 8) = pk;
        }
    }
    if (tid < 48) {
        int g = tid >> 4, jj = tid & 15;
        bh[tid] = (is_l1 ? bhh1 : bhh0)[g * 1024 + jbase + jj];
        bi[tid] = is_l1 ? bih1[g * 1024 + jbase + jj] : 0.f;
    }
    hp32[tid] = 0.f;
    if (tid == 0) { sflagA = 0u; sflagB = 0u; }
    __syncthreads();

    // ---- W_hh fragments in registers (6 n-octets x 8 k-frags) ----
    uint32_t wf[6][8][2];
    {
        const float* W = is_l1 ? Whh1 : Whh0;
        const int nr = lane >> 2, kq = (lane & 3) * 2;
#pragma unroll
        for (int o = 0; o < 6; o++) {
            const float* wrow = W + (size_t)((o >> 1) * 1024 + jbase + (o & 1) * 8 + nr) * 1024
                              + warp * 128 + kq;
#pragma unroll
            for (int kt = 0; kt < 8; kt++) {
                float2 lo = *(const float2*)(wrow + kt * 16);
                float2 hi = *(const float2*)(wrow + kt * 16 + 8);
                wf[o][kt][0] = pk_bf16x2(lo.x, lo.y);
                wf[o][kt][1] = pk_bf16x2(hi.x, hi.y);
            }
        }
    }

    const uint32_t hs_b  = smem_u32(hs);
    const uint32_t a_base = hs_b + (uint32_t)((lane & 15) * HROW + (lane >> 4) * 16 + warp * 256);
    const uint32_t wihb = smem_u32(wih) + (uint32_t)(warp * 256
                         + (((lane >> 4) & 1) * 8 + (lane & 7)) * HROW
                         + ((lane >> 3) & 1) * 16);
    const int st_b0 = lane >> 4;
    const int st_c  = lane & 15;

    if (!is_l1) {
        // ================= layer 0 =================
        for (int t = 0; t < TSEQ; t++) {
            // prefetch gx0 (hides behind the wait)
            float xr, xz, xn;
            {
                int jj = tid & 15, b = tid >> 4;
                const float* gp = gx0 + ((size_t)((b << 10) + t)) * 3072 + jbase + jj;
                xr = gp[0]; xz = gp[1024]; xn = gp[2048];
            }
            if (t > 0) {
                if (tid == 0) {
                    while (ld_acq(cnt0) < 64u * (unsigned)t) { }
                    sflagA = (unsigned)t;
                } else if (lane == 0) {
                    while (sflagA < (unsigned)t) { }
                }
                __syncwarp();
            }
            // stage own K-slice of h1_{t-1}
            if (t == 0) {
#pragma unroll
                for (int l = 0; l < 8; l++) {
                    int b = st_b0 + l * 2;
                    *(uint4*)(hs + b * HROW + warp * 256 + st_c * 16) = make_uint4(0, 0, 0, 0);
                }
            } else {
#pragma unroll
                for (int l = 0; l < 8; l++) {
                    int b = st_b0 + l * 2;
                    uint4 v = __ldcg((const uint4*)(h1 + ((size_t)((b << 10) + (t - 1))) * 1024
                                                    + warp * 128 + st_c * 8));
                    *(uint4*)(hs + b * HROW + warp * 256 + st_c * 16) = v;
                }
            }
            __syncwarp();

            float acc[6][4];
#pragma unroll
            for (int o = 0; o < 6; o++)
#pragma unroll
                for (int i = 0; i < 4; i++) acc[o][i] = 0.f;
#pragma unroll
            for (int kt = 0; kt < 8; kt++) {
                uint32_t a[4];
                ldsm_x4(a, a_base + kt * 32);
#pragma unroll
                for (int o = 0; o < 6; o++)
                    mma16(acc[o], a, wf[o][kt][0], wf[o][kt][1]);
            }
            {
                float* pw = part + warp * (16 * PSTRIDE);
                const int r = lane >> 2, c2 = (lane & 3) * 2;
#pragma unroll
                for (int o = 0; o < 6; o++) {
                    *(float2*)(pw + r * PSTRIDE + o * 8 + c2)       = make_float2(acc[o][0], acc[o][1]);
                    *(float2*)(pw + (r + 8) * PSTRIDE + o * 8 + c2) = make_float2(acc[o][2], acc[o][3]);
                }
            }
            __syncthreads();
            {
                int jj = tid & 15, b = tid >> 4;
                float sr = bh[jj], sz = bh[16 + jj], sn = bh[32 + jj];
#pragma unroll
                for (int w = 0; w < 8; w++) {
                    const float* p = part + w * (16 * PSTRIDE) + b * PSTRIDE;
                    sr += p[jj]; sz += p[16 + jj]; sn += p[32 + jj];
                }
                float rg = 1.f / (1.f + expf(-(xr + sr)));
                float zg = 1.f / (1.f + expf(-(xz + sz)));
                float ng = tanhf(xn + rg * sn);
                float hnew = (1.f - zg) * ng + zg * hp32[tid];
                hp32[tid] = hnew;
                __stcg(h1 + ((size_t)((b << 10) + t)) * 1024 + jbase + jj, __float2bfloat16(hnew));
            }
            __syncthreads();
            if (tid == 0) red_rel(cnt0);
        }
    } else {
        // ================= layer 1 (lags layer 0) =================
        for (int t = 0; t < TSEQ; t++) {
            if (tid == 0) {
                while (ld_acq(cnt0) < 64u * (unsigned)(t + 1)) { }
                sflagA = (unsigned)(t + 1);
                if (t > 0) {
                    while (ld_acq(cnt1) < 64u * (unsigned)t) { }
                }
                sflagB = (unsigned)(t + 1);
            } else if (lane == 0) {
                while (sflagA < (unsigned)(t + 1)) { }
            }
            __syncwarp();

            // ---- pass 1: input gates from h1_t, W_ih1 (smem) ----
#pragma unroll
            for (int l = 0; l < 8; l++) {
                int b = st_b0 + l * 2;
                uint4 v = __ldcg((const uint4*)(h1 + ((size_t)((b << 10) + t)) * 1024
                                                + warp * 128 + st_c * 8));
                *(uint4*)(hs + b * HROW + warp * 256 + st_c * 16) = v;
            }
            __syncwarp();

            float acc[6][4], accN[2][4];
#pragma unroll
            for (int o = 0; o < 6; o++)
#pragma unroll
                for (int i = 0; i < 4; i++) acc[o][i] = 0.f;
#pragma unroll
            for (int o = 0; o < 2; o++)
#pragma unroll
                for (int i = 0; i < 4; i++) accN[o][i] = 0.f;

#pragma unroll
            for (int kt = 0; kt < 8; kt++) {
                uint32_t a[4];
                ldsm_x4(a, a_base + kt * 32);
#pragma unroll
                for (int p = 0; p < 3; p++) {
                    uint32_t bf[4];
                    ldsm_x4(bf, wihb + p * 16 * HROW + kt * 32);
                    mma16(acc[2 * p],     a, bf[0], bf[1]);
                    mma16(acc[2 * p + 1], a, bf[2], bf[3]);
                }
            }

            // ---- wait own h2_{t-1}, pass 2: recurrent ----
            if (lane == 0 && tid != 0) {
                while (sflagB < (unsigned)(t + 1)) { }
            }
            __syncwarp();
            if (t == 0) {
#pragma unroll
                for (int l = 0; l < 8; l++) {
                    int b = st_b0 + l * 2;
                    *(uint4*)(hs + b * HROW + warp * 256 + st_c * 16) = make_uint4(0, 0, 0, 0);
                }
            } else {
#pragma unroll
                for (int l = 0; l < 8; l++) {
                    int b = st_b0 + l * 2;
                    uint4 v = __ldcg((const uint4*)(h2 + ((size_t)((b << 10) + (t - 1))) * 1024
                                                    + warp * 128 + st_c * 8));
                    *(uint4*)(hs + b * HROW + warp * 256 + st_c * 16) = v;
                }
            }
            __syncwarp();

#pragma unroll
            for (int kt = 0; kt < 8; kt++) {
                uint32_t a[4];
                ldsm_x4(a, a_base + kt * 32);
#pragma unroll
                for (int o = 0; o < 4; o++)
                    mma16(acc[o], a, wf[o][kt][0], wf[o][kt][1]);
                mma16(accN[0], a, wf[4][kt][0], wf[4][kt][1]);
                mma16(accN[1], a, wf[5][kt][0], wf[5][kt][1]);
            }

            // partial store: cols [0:16) r, [16:32) z, [32:48) n_in, [48:64) n_rec
            {
                float* pw = part + warp * (16 * PSTRIDE);
                const int r = lane >> 2, c2 = (lane & 3) * 2;
#pragma unroll
                for (int o = 0; o < 6; o++) {
                    *(float2*)(pw + r * PSTRIDE + o * 8 + c2)       = make_float2(acc[o][0], acc[o][1]);
                    *(float2*)(pw + (r + 8) * PSTRIDE + o * 8 + c2) = make_float2(acc[o][2], acc[o][3]);
                }
#pragma unroll
                for (int o = 0; o < 2; o++) {
                    *(float2*)(pw + r * PSTRIDE + 48 + o * 8 + c2)       = make_float2(accN[o][0], accN[o][1]);
                    *(float2*)(pw + (r + 8) * PSTRIDE + 48 + o * 8 + c2) = make_float2(accN[o][2], accN[o][3]);
                }
            }
            __syncthreads();
            {
                int jj = tid & 15, b = tid >> 4;
                float sr = bi[jj] + bh[jj];
                float sz = bi[16 + jj] + bh[16 + jj];
                float xn = bi[32 + jj];
                float hn = bh[32 + jj];
#pragma unroll
                for (int w = 0; w < 8; w++) {
                    const float* p = part + w * (16 * PSTRIDE) + b * PSTRIDE;
                    sr += p[jj]; sz += p[16 + jj]; xn += p[32 + jj]; hn += p[48 + jj];
                }
                float rg = 1.f / (1.f + expf(-sr));
                float zg = 1.f / (1.f + expf(-sz));
                float ng = tanhf(xn + rg * hn);
                float hnew = (1.f - zg) * ng + zg * hp32[tid];
                hp32[tid] = hnew;
                __stcg(h2 + ((size_t)((b << 10) + t)) * 1024 + jbase + jj, __float2bfloat16(hnew));
            }
            __syncthreads();
            if (tid == 0) red_rel(cnt1);
        }
    }
}

// ===========================================================================
// log_softmax over axis=1 (T)
// ===========================================================================
__global__ void __launch_bounds__(1024) lse_kernel(
    const float* __restrict__ logits, float* __restrict__ lse)
{
    __shared__ float sm_m[1024], sm_s[1024];
    const int b = blockIdx.x;
    const int tid = threadIdx.x;
    const int c = tid & 127, ts = tid >> 7;
    const float* p = logits + ((size_t)((b << 10) + (ts << 7))) * NCLS + c;
    float m = -1e30f, s = 0.f;
    for (int i = 0; i < 128; i++) {
        float x = p[(size_t)i * NCLS];
        if (x > m) { s = s * expf(m - x) + 1.f; m = x; }
        else       { s += expf(x - m); }
    }
    sm_m[tid] = m; sm_s[tid] = s;
    __syncthreads();
    if (tid < 128) {
        float M = sm_m[tid], S = sm_s[tid];
#pragma unroll
        for (int k = 1; k < 8; k++) {
            float m2 = sm_m[tid + k * 128], s2 = sm_s[tid + k * 128];
            if (m2 > M) { S = S * expf(M - m2) + s2; M = m2; }
            else        { S += s2 * expf(m2 - M); }
        }
        lse[b * NCLS + tid] = M + logf(S);
    }
}

__global__ void sub_kernel(float* __restrict__ out, const float* __restrict__ lse)
{
    int idx = blockIdx.x * blockDim.x + threadIdx.x;
    int b = idx >> 17;
    int c = idx & 127;
    out[idx] -= lse[(b << 7) + c];
}

// ===========================================================================
extern "C" void kernel_launch(void* const* d_in, const int* in_sizes, int n_in,
                              void* d_out, int out_size)
{
    (void)in_sizes; (void)n_in; (void)out_size;
    const int*   tok  = (const int*)d_in[0];
    const float* emb  = (const float*)d_in[1];
    const float* Wih0 = (const float*)d_in[2];
    const float* Whh0 = (const float*)d_in[3];
    const float* bih0 = (const float*)d_in[4];
    const float* bhh0 = (const float*)d_in[5];
    const float* Wih1 = (const float*)d_in[6];
    const float* Whh1 = (const float*)d_in[7];
    const float* bih1 = (const float*)d_in[8];
    const float* bhh1 = (const float*)d_in[9];
    const float* Wlin = (const float*)d_in[10];
    const float* blin = (const float*)d_in[11];
    float* out = (float*)d_out;

    float *gx, *lseb;
    __nv_bfloat16 *h1, *h2, *a16, *b16;
    cudaGetSymbolAddress((void**)&gx,   g_gx);
    cudaGetSymbolAddress((void**)&lseb, g_lse);
    cudaGetSymbolAddress((void**)&h1,   g_h1);
    cudaGetSymbolAddress((void**)&h2,   g_h2);
    cudaGetSymbolAddress((void**)&a16,  g_a16);
    cudaGetSymbolAddress((void**)&b16,  g_b16);

    cudaFuncSetAttribute(gemm_bf16, cudaFuncAttributeMaxDynamicSharedMemorySize,
                         GEMM_SMEM_BYTES);
    cudaFuncSetAttribute(scan_fused, cudaFuncAttributeMaxDynamicSharedMemorySize,
                         SM_TOTAL);

    const size_t a_tot4 = ((size_t)MTOT * HD) / 4;
    const size_t w_tot4 = ((size_t)G3H * HD) / 4;
    const size_t l_tot4 = ((size_t)NCLS * HD) / 4;
    const int CB = 256;

    dim3 gG(MTOT / 128, G3H / 128);   // (128, 24)
    dim3 gL(MTOT / 128, 1);

    // Layer-0 input gates: gx0 = emb[tok] @ Wih0^T + bih0
    conv_bf16<<<(unsigned)((a_tot4 + CB - 1) / CB), CB>>>(emb, tok, a16, a_tot4);
    conv_bf16<<<(unsigned)((w_tot4 + CB - 1) / CB), CB>>>(Wih0, nullptr, b16, w_tot4);
    gemm_bf16<<<gG, 256, GEMM_SMEM_BYTES>>>(a16, b16, bih0, gx, G3H);

    // Fused pipelined scans (both layers)
    bar_reset<<<1, 1>>>();
    scan_fused<<<128, 256, SM_TOTAL>>>(gx, Whh0, bhh0, Wih1, bih1, Whh1, bhh1, h1, h2);

    // Head
    conv_bf16<<<(unsigned)((l_tot4 + CB - 1) / CB), CB>>>(Wlin, nullptr, b16, l_tot4);
    gemm_bf16<<<gL, 256, GEMM_SMEM_BYTES>>>(h2, b16, blin, out, NCLS);

    // log_softmax over T
    lse_kernel<<<BATCH, 1024>>>(out, lseb);
    sub_kernel<<<(MTOT * NCLS) / 1024, 1024>>>(out, lseb);
}

// round 11
// speedup vs baseline: 12.7015x; 1.3744x over previous
#include <cuda_runtime.h>
#include <cuda_bf16.h>
#include <cstdint>
#include <math.h>

#define BATCH 16
#define TSEQ  1024
#define HD    1024
#define MTOT  (BATCH * TSEQ)   // 16384
#define G3H   (3 * HD)         // 3072
#define NCLS  128

__device__ __nv_bfloat16 g_h1[(size_t)MTOT * HD];    // layer-0 hidden seq
__device__ __nv_bfloat16 g_h2[(size_t)MTOT * HD];    // layer-1 hidden seq
__device__ __nv_bfloat16 g_a16[(size_t)MTOT * HD];   // gathered emb (bf16)
__device__ __nv_bfloat16 g_b16[(size_t)G3H * HD];    // head weights bf16
__device__ float g_lse[BATCH * NCLS];
__device__ unsigned g_cntv[128 * 32];                // per-CTA step counters (128B stride)

// ===========================================================================
// fp32 -> bf16 convert (optionally gathering rows via tok); rows are K=1024
// ===========================================================================
__global__ void __launch_bounds__(256) conv_bf16(
    const float* __restrict__ in, const int* __restrict__ tok,
    __nv_bfloat16* __restrict__ out, size_t total4)
{
    size_t idx = (size_t)blockIdx.x * blockDim.x + threadIdx.x;
    if (idx >= total4) return;
    size_t e = idx << 2;
    size_t m = e >> 10;
    int    k = (int)(e & 1023);
    size_t srow = tok ? (size_t)tok[m] : m;
    float4 v = *(const float4*)(in + srow * 1024 + k);
    __nv_bfloat162 p0 = __floats2bfloat162_rn(v.x, v.y);
    __nv_bfloat162 p1 = __floats2bfloat162_rn(v.z, v.w);
    *(__nv_bfloat162*)(out + e)     = p0;
    *(__nv_bfloat162*)(out + e + 2) = p1;
}

// ===========================================================================
// Shared helpers
// ===========================================================================
__device__ __forceinline__ uint32_t smem_u32(const void* p) {
    uint32_t a;
    asm("{ .reg .u64 t; cvta.to.shared.u64 t, %1; cvt.u32.u64 %0, t; }"
        : "=r"(a) : "l"(p));
    return a;
}

__device__ __forceinline__ void ldsm_x4(uint32_t* r, uint32_t addr) {
    asm volatile("ldmatrix.sync.aligned.m8n8.x4.shared.b16 {%0,%1,%2,%3}, [%4];"
                 : "=r"(r[0]), "=r"(r[1]), "=r"(r[2]), "=r"(r[3]) : "r"(addr));
}

__device__ __forceinline__ void mma16(float* d, const uint32_t* a, uint32_t b0, uint32_t b1) {
    asm volatile(
        "mma.sync.aligned.m16n8k16.row.col.f32.bf16.bf16.f32 "
        "{%0,%1,%2,%3}, {%4,%5,%6,%7}, {%8,%9}, {%0,%1,%2,%3};"
        : "+f"(d[0]), "+f"(d[1]), "+f"(d[2]), "+f"(d[3])
        : "r"(a[0]), "r"(a[1]), "r"(a[2]), "r"(a[3]), "r"(b0), "r"(b1));
}

__device__ __forceinline__ uint32_t pk_bf16x2(float lo, float hi) {
    __nv_bfloat162 p = __floats2bfloat162_rn(lo, hi);
    return *reinterpret_cast<uint32_t*>(&p);
}

__device__ __forceinline__ unsigned ld_acq(const unsigned* p) {
    unsigned v;
    asm volatile("ld.acquire.gpu.global.u32 %0, [%1];" : "=r"(v) : "l"(p) : "memory");
    return v;
}

__device__ __forceinline__ void st_rel(unsigned* p, unsigned v) {
    asm volatile("st.release.gpu.global.u32 [%0], %1;" :: "l"(p), "r"(v) : "memory");
}

// ===========================================================================
// bf16 mma.sync GEMM (validated R7) — used only for the head now
// ===========================================================================
#define RSTR_B 144
#define TILE_B (128 * RSTR_B)
#define GEMM_SMEM_BYTES (4 * TILE_B)

__global__ void __launch_bounds__(256) gemm_bf16(
    const __nv_bfloat16* __restrict__ A16,
    const __nv_bfloat16* __restrict__ B16,
    const float* __restrict__ bias,
    float* __restrict__ C, int N)
{
    extern __shared__ char smc[];
    const uint32_t sbase = smem_u32(smc);
    const int tid  = threadIdx.x;
    const int lane = tid & 31;
    const int warp = tid >> 5;
    const int bm = blockIdx.x * 128;
    const int bn = blockIdx.y * 128;
    const int wm = (warp & 1) * 64;
    const int wn = (warp >> 1) * 32;
    const int qr = lane >> 2;
    const int qc = lane & 3;

    const int r0 = tid >> 3;
    const int ch = tid & 7;
    const __nv_bfloat16* Ap = A16 + (size_t)(bm + r0) * 1024 + ch * 8;
    const __nv_bfloat16* Bp = B16 + (size_t)(bn + r0) * 1024 + ch * 8;
    const uint32_t s_off = (uint32_t)(r0 * RSTR_B + ch * 16);

    const uint32_t a_lm = (uint32_t)((wm + (lane & 15)) * RSTR_B + (lane >> 4) * 16);
    const uint32_t b_lm = (uint32_t)((wn + ((lane >> 4) & 1) * 8 + (lane & 7)) * RSTR_B
                                     + ((lane >> 3) & 1) * 16);

    float acc[4][4][4];
#pragma unroll
    for (int mf = 0; mf < 4; mf++)
#pragma unroll
        for (int nf = 0; nf < 4; nf++)
#pragma unroll
            for (int i = 0; i < 4; i++) acc[mf][nf][i] = 0.f;

    uint4 ra[4], rb[4];
#pragma unroll
    for (int l = 0; l < 4; l++) {
        ra[l] = *(const uint4*)(Ap + l * 32 * 1024);
        rb[l] = *(const uint4*)(Bp + l * 32 * 1024);
    }

    for (int it = 0; it < 16; it++) {
        const int buf = it & 1;
        const uint32_t abase = buf * (2 * TILE_B);
        const uint32_t bbase = abase + TILE_B;

#pragma unroll
        for (int l = 0; l < 4; l++) {
            *(uint4*)(smc + abase + s_off + l * 32 * RSTR_B) = ra[l];
            *(uint4*)(smc + bbase + s_off + l * 32 * RSTR_B) = rb[l];
        }
        __syncthreads();

        if (it + 1 < 16) {
            const size_t kofs = (size_t)(it + 1) * 64;
#pragma unroll
            for (int l = 0; l < 4; l++) {
                ra[l] = *(const uint4*)(Ap + l * 32 * 1024 + kofs);
                rb[l] = *(const uint4*)(Bp + l * 32 * 1024 + kofs);
            }
        }

        const uint32_t sA = sbase + abase + a_lm;
        const uint32_t sB = sbase + bbase + b_lm;
#pragma unroll
        for (int ks = 0; ks < 4; ks++) {
            uint32_t af[4][4], bb[2][4];
#pragma unroll
            for (int mf = 0; mf < 4; mf++)
                ldsm_x4(af[mf], sA + mf * 16 * RSTR_B + ks * 32);
#pragma unroll
            for (int np = 0; np < 2; np++)
                ldsm_x4(bb[np], sB + np * 16 * RSTR_B + ks * 32);
#pragma unroll
            for (int mf = 0; mf < 4; mf++) {
                mma16(acc[mf][0], af[mf], bb[0][0], bb[0][1]);
                mma16(acc[mf][1], af[mf], bb[0][2], bb[0][3]);
                mma16(acc[mf][2], af[mf], bb[1][0], bb[1][1]);
                mma16(acc[mf][3], af[mf], bb[1][2], bb[1][3]);
            }
        }
    }

#pragma unroll
    for (int nf = 0; nf < 4; nf++) {
        const int c = bn + wn + nf * 8 + 2 * qc;
        const float b0 = bias[c], b1 = bias[c + 1];
#pragma unroll
        for (int mf = 0; mf < 4; mf++) {
            const int rr = bm + wm + mf * 16 + qr;
            float2 v0 = make_float2(acc[mf][nf][0] + b0, acc[mf][nf][1] + b1);
            float2 v1 = make_float2(acc[mf][nf][2] + b0, acc[mf][nf][3] + b1);
            *(float2*)(C + (size_t)rr * N + c) = v0;
            *(float2*)(C + (size_t)(rr + 8) * N + c) = v1;
        }
    }
}

// ===========================================================================
// Fully fused two-layer pipelined GRU scan (both input and recurrent GEMMs
// per step). Grid = 128 CTAs x 256 threads; CTAs 0..63 layer-0 (pass-1 input
// = gathered emb), 64..127 layer-1 (pass-1 input = h1, lagging one step).
// Per-CTA release counters; consumer warp w waits only on its 8 producers.
// ===========================================================================
#define L0_CTAS 64
#define HROW 2064                 // smem row stride bytes (1032 bf16)
#define PSTRIDE 66                // part row stride floats
#define SM_HS    0                // 16 * 2064 = 33024
#define SM_WIH   33024            // 48 * 2064 = 99072
#define SM_PART  132096           // 8 * 16 * 66 * 4 = 33792
#define SM_BI    165888           // 48 * 4
#define SM_BH    166080           // 48 * 4
#define SM_HP    166272           // 256 * 4
#define SM_TOTAL 167296

__global__ void bar_reset() {
    for (int i = threadIdx.x; i < 128 * 32; i += blockDim.x) g_cntv[i] = 0u;
}

__global__ void __launch_bounds__(256, 1) scan_fused(
    const __nv_bfloat16* __restrict__ a16,
    const float* __restrict__ Wih0, const float* __restrict__ bih0,
    const float* __restrict__ Whh0, const float* __restrict__ bhh0,
    const float* __restrict__ Wih1, const float* __restrict__ bih1,
    const float* __restrict__ Whh1, const float* __restrict__ bhh1,
    __nv_bfloat16* __restrict__ h1, __nv_bfloat16* __restrict__ h2)
{
    extern __shared__ char dsm[];
    char*  hs   = dsm + SM_HS;
    char*  wih  = dsm + SM_WIH;
    float* part = (float*)(dsm + SM_PART);
    float* bi   = (float*)(dsm + SM_BI);
    float* bh   = (float*)(dsm + SM_BH);
    float* hp32 = (float*)(dsm + SM_HP);

    const int tid  = threadIdx.x;
    const int lane = tid & 31;
    const int warp = tid >> 5;
    const bool is_l1 = blockIdx.x >= L0_CTAS;
    const int jbase = (is_l1 ? (int)blockIdx.x - L0_CTAS : (int)blockIdx.x) * 16;

    unsigned* cnt_l0 = g_cntv;                 // slots 0..63  (stride 32)
    unsigned* cnt_l1 = g_cntv + 64 * 32;       // slots 64..127
    unsigned* my_cnt = g_cntv + (int)blockIdx.x * 32;
    unsigned* cnt_p1 = is_l1 ? cnt_l0 : (unsigned*)nullptr;   // pass-1 producers
    unsigned* cnt_p2 = is_l1 ? cnt_l1 : cnt_l0;               // pass-2 producers

    const __nv_bfloat16* xin   = is_l1 ? h1 : a16;    // pass-1 input rows
    const __nv_bfloat16* hprev = is_l1 ? h2 : h1;     // pass-2 input rows
    __nv_bfloat16*       hout  = is_l1 ? h2 : h1;

    // ---- One-time setup: W_ih rows (48) -> smem bf16 ----
    {
        const float* Wih = is_l1 ? Wih1 : Wih0;
        for (int f = tid; f < 48 * 256; f += 256) {
            int n = f >> 8, c4 = f & 255;
            int g = n >> 4, jj = n & 15;
            float4 v = *(const float4*)(Wih + (size_t)(g * 1024 + jbase + jj) * 1024 + c4 * 4);
            uint2 pk;
            pk.x = pk_bf16x2(v.x, v.y);
            pk.y = pk_bf16x2(v.z, v.w);
            *(uint2*)(wih + n * HROW + c4 * 8) = pk;
        }
    }
    if (tid < 48) {
        int g = tid >> 4, jj = tid & 15;
        bi[tid] = (is_l1 ? bih1 : bih0)[g * 1024 + jbase + jj];
        bh[tid] = (is_l1 ? bhh1 : bhh0)[g * 1024 + jbase + jj];
    }
    hp32[tid] = 0.f;
    __syncthreads();

    // ---- W_hh fragments in registers (6 n-octets x 8 k-frags) ----
    uint32_t wf[6][8][2];
    {
        const float* W = is_l1 ? Whh1 : Whh0;
        const int nr = lane >> 2, kq = (lane & 3) * 2;
#pragma unroll
        for (int o = 0; o < 6; o++) {
            const float* wrow = W + (size_t)((o >> 1) * 1024 + jbase + (o & 1) * 8 + nr) * 1024
                              + warp * 128 + kq;
#pragma unroll
            for (int kt = 0; kt < 8; kt++) {
                float2 lo = *(const float2*)(wrow + kt * 16);
                float2 hi = *(const float2*)(wrow + kt * 16 + 8);
                wf[o][kt][0] = pk_bf16x2(lo.x, lo.y);
                wf[o][kt][1] = pk_bf16x2(hi.x, hi.y);
            }
        }
    }

    const uint32_t hs_b   = smem_u32(hs);
    const uint32_t a_base = hs_b + (uint32_t)((lane & 15) * HROW + (lane >> 4) * 16 + warp * 256);
    const uint32_t wihb   = smem_u32(wih) + (uint32_t)(warp * 256
                           + (((lane >> 4) & 1) * 8 + (lane & 7)) * HROW
                           + ((lane >> 3) & 1) * 16);
    const int st_b0 = lane >> 4;
    const int st_c  = lane & 15;
    const int pslot = (warp * 8 + (lane & 7)) * 32;   // lanes 0..7 poll producers

    for (int t = 0; t < TSEQ; t++) {
        // ======== pass 1: input gates (x_t @ W_ih^T) ========
        if (is_l1) {
            if (lane < 8) {
                const unsigned* cp = cnt_p1 + pslot;
                while (ld_acq(cp) < (unsigned)(t + 1)) { }
            }
            __syncwarp();
        }
#pragma unroll
        for (int l = 0; l < 8; l++) {
            int b = st_b0 + l * 2;
            uint4 v = __ldcg((const uint4*)(xin + ((size_t)((b << 10) + t)) * 1024
                                            + warp * 128 + st_c * 8));
            *(uint4*)(hs + b * HROW + warp * 256 + st_c * 16) = v;
        }
        __syncwarp();

        float acc[6][4], accN[2][4];
#pragma unroll
        for (int o = 0; o < 6; o++)
#pragma unroll
            for (int i = 0; i < 4; i++) acc[o][i] = 0.f;
#pragma unroll
        for (int o = 0; o < 2; o++)
#pragma unroll
            for (int i = 0; i < 4; i++) accN[o][i] = 0.f;

#pragma unroll
        for (int kt = 0; kt < 8; kt++) {
            uint32_t a[4];
            ldsm_x4(a, a_base + kt * 32);
#pragma unroll
            for (int p = 0; p < 3; p++) {
                uint32_t bf[4];
                ldsm_x4(bf, wihb + p * 16 * HROW + kt * 32);
                mma16(acc[2 * p],     a, bf[0], bf[1]);
                mma16(acc[2 * p + 1], a, bf[2], bf[3]);
            }
        }

        // ======== pass 2: recurrent gates (h_{t-1} @ W_hh^T) ========
        if (t > 0) {
            if (lane < 8) {
                const unsigned* cp = cnt_p2 + pslot;
                while (ld_acq(cp) < (unsigned)t) { }
            }
            __syncwarp();
#pragma unroll
            for (int l = 0; l < 8; l++) {
                int b = st_b0 + l * 2;
                uint4 v = __ldcg((const uint4*)(hprev + ((size_t)((b << 10) + (t - 1))) * 1024
                                                + warp * 128 + st_c * 8));
                *(uint4*)(hs + b * HROW + warp * 256 + st_c * 16) = v;
            }
        } else {
#pragma unroll
            for (int l = 0; l < 8; l++) {
                int b = st_b0 + l * 2;
                *(uint4*)(hs + b * HROW + warp * 256 + st_c * 16) = make_uint4(0, 0, 0, 0);
            }
        }
        __syncwarp();

#pragma unroll
        for (int kt = 0; kt < 8; kt++) {
            uint32_t a[4];
            ldsm_x4(a, a_base + kt * 32);
#pragma unroll
            for (int o = 0; o < 4; o++)
                mma16(acc[o], a, wf[o][kt][0], wf[o][kt][1]);
            mma16(accN[0], a, wf[4][kt][0], wf[4][kt][1]);
            mma16(accN[1], a, wf[5][kt][0], wf[5][kt][1]);
        }

        // partial store: cols [0:16) r, [16:32) z, [32:48) n_in, [48:64) n_rec
        {
            float* pw = part + warp * (16 * PSTRIDE);
            const int r = lane >> 2, c2 = (lane & 3) * 2;
#pragma unroll
            for (int o = 0; o < 6; o++) {
                *(float2*)(pw + r * PSTRIDE + o * 8 + c2)       = make_float2(acc[o][0], acc[o][1]);
                *(float2*)(pw + (r + 8) * PSTRIDE + o * 8 + c2) = make_float2(acc[o][2], acc[o][3]);
            }
#pragma unroll
            for (int o = 0; o < 2; o++) {
                *(float2*)(pw + r * PSTRIDE + 48 + o * 8 + c2)       = make_float2(accN[o][0], accN[o][1]);
                *(float2*)(pw + (r + 8) * PSTRIDE + 48 + o * 8 + c2) = make_float2(accN[o][2], accN[o][3]);
            }
        }
        __syncthreads();

        // ======== gates ========
        {
            int jj = tid & 15, b = tid >> 4;
            float sr = bi[jj] + bh[jj];
            float sz = bi[16 + jj] + bh[16 + jj];
            float xn = bi[32 + jj];
            float hn = bh[32 + jj];
#pragma unroll
            for (int w = 0; w < 8; w++) {
                const float* p = part + w * (16 * PSTRIDE) + b * PSTRIDE;
                sr += p[jj]; sz += p[16 + jj]; xn += p[32 + jj]; hn += p[48 + jj];
            }
            float rg = 1.f / (1.f + expf(-sr));
            float zg = 1.f / (1.f + expf(-sz));
            float ng = tanhf(xn + rg * hn);
            float hnew = (1.f - zg) * ng + zg * hp32[tid];
            hp32[tid] = hnew;
            __stcg(hout + ((size_t)((b << 10) + t)) * 1024 + jbase + jj, __float2bfloat16(hnew));
        }
        __syncthreads();
        if (tid == 0) st_rel(my_cnt, (unsigned)(t + 1));
    }
}

// ===========================================================================
// log_softmax over axis=1 (T)
// ===========================================================================
__global__ void __launch_bounds__(1024) lse_kernel(
    const float* __restrict__ logits, float* __restrict__ lse)
{
    __shared__ float sm_m[1024], sm_s[1024];
    const int b = blockIdx.x;
    const int tid = threadIdx.x;
    const int c = tid & 127, ts = tid >> 7;
    const float* p = logits + ((size_t)((b << 10) + (ts << 7))) * NCLS + c;
    float m = -1e30f, s = 0.f;
    for (int i = 0; i < 128; i++) {
        float x = p[(size_t)i * NCLS];
        if (x > m) { s = s * expf(m - x) + 1.f; m = x; }
        else       { s += expf(x - m); }
    }
    sm_m[tid] = m; sm_s[tid] = s;
    __syncthreads();
    if (tid < 128) {
        float M = sm_m[tid], S = sm_s[tid];
#pragma unroll
        for (int k = 1; k < 8; k++) {
            float m2 = sm_m[tid + k * 128], s2 = sm_s[tid + k * 128];
            if (m2 > M) { S = S * expf(M - m2) + s2; M = m2; }
            else        { S += s2 * expf(m2 - M); }
        }
        lse[b * NCLS + tid] = M + logf(S);
    }
}

__global__ void sub_kernel(float* __restrict__ out, const float* __restrict__ lse)
{
    int idx = blockIdx.x * blockDim.x + threadIdx.x;
    int b = idx >> 17;
    int c = idx & 127;
    out[idx] -= lse[(b << 7) + c];
}

// ===========================================================================
extern "C" void kernel_launch(void* const* d_in, const int* in_sizes, int n_in,
                              void* d_out, int out_size)
{
    (void)in_sizes; (void)n_in; (void)out_size;
    const int*   tok  = (const int*)d_in[0];
    const float* emb  = (const float*)d_in[1];
    const float* Wih0 = (const float*)d_in[2];
    const float* Whh0 = (const float*)d_in[3];
    const float* bih0 = (const float*)d_in[4];
    const float* bhh0 = (const float*)d_in[5];
    const float* Wih1 = (const float*)d_in[6];
    const float* Whh1 = (const float*)d_in[7];
    const float* bih1 = (const float*)d_in[8];
    const float* bhh1 = (const float*)d_in[9];
    const float* Wlin = (const float*)d_in[10];
    const float* blin = (const float*)d_in[11];
    float* out = (float*)d_out;

    float *lseb;
    __nv_bfloat16 *h1, *h2, *a16, *b16;
    cudaGetSymbolAddress((void**)&lseb, g_lse);
    cudaGetSymbolAddress((void**)&h1,   g_h1);
    cudaGetSymbolAddress((void**)&h2,   g_h2);
    cudaGetSymbolAddress((void**)&a16,  g_a16);
    cudaGetSymbolAddress((void**)&b16,  g_b16);

    cudaFuncSetAttribute(gemm_bf16, cudaFuncAttributeMaxDynamicSharedMemorySize,
                         GEMM_SMEM_BYTES);
    cudaFuncSetAttribute(scan_fused, cudaFuncAttributeMaxDynamicSharedMemorySize,
                         SM_TOTAL);

    const size_t a_tot4 = ((size_t)MTOT * HD) / 4;
    const size_t l_tot4 = ((size_t)NCLS * HD) / 4;
    const int CB = 256;

    // Prologue: gather emb -> bf16, convert head weights -> bf16, zero counters
    conv_bf16<<<(unsigned)((a_tot4 + CB - 1) / CB), CB>>>(emb, tok, a16, a_tot4);
    conv_bf16<<<(unsigned)((l_tot4 + CB - 1) / CB), CB>>>(Wlin, nullptr, b16, l_tot4);
    bar_reset<<<1, 256>>>();

    // Fused two-layer scan (includes both layers' input GEMMs)
    scan_fused<<<128, 256, SM_TOTAL>>>(a16, Wih0, bih0, Whh0, bhh0,
                                       Wih1, bih1, Whh1, bhh1, h1, h2);

    // Head
    dim3 gL(MTOT / 128, 1);
    gemm_bf16<<<gL, 256, GEMM_SMEM_BYTES>>>(h2, b16, blin, out, NCLS);

    // log_softmax over T
    lse_kernel<<<BATCH, 1024>>>(out, lseb);
    sub_kernel<<<(MTOT * NCLS) / 1024, 1024>>>(out, lseb);
}